// round 8
// baseline (speedup 1.0000x reference)
#include <cuda_runtime.h>
#include <math.h>
#include <float.h>

#define H 256
#define G_ 256
#define H2 512
#define E_MAX 524288
#define GT 8                            // graphs per block in k_head
#define RUN_CAP 8192
#define LOGEPS -15.942385152878742f     // logf(FLT_EPSILON)

// ---------------- scratch (static device globals; no allocation) ----------------
__device__ float    d_att[E_MAX];      // att score (candidates); -1e38 for selected
__device__ float    d_sumtok[G_ * H];  // segment sum of edge_tokens
__device__ int      d_cnt[G_];         // edges per graph
__device__ unsigned d_gmax[G_];        // ordered-uint encoded segment max
__device__ float    d_off[G_];         // gmax + log(gsum) per graph
__device__ float    d_u[H];            // att_vec @ W_edge
__device__ float    d_v[H];            // att_vec @ W_query
__device__ float    d_qatt[G_];        // question_tokens @ v
__device__ int      d_nrun;            // run record counter
__device__ int      d_rg[RUN_CAP];     // run graph id
__device__ float    d_rm[RUN_CAP];     // run max
__device__ float    d_rs[RUN_CAP];     // run expsum (relative to run max)

__device__ __forceinline__ unsigned f2ord(float f) {
    unsigned b = __float_as_uint(f);
    return (b & 0x80000000u) ? ~b : (b | 0x80000000u);
}
__device__ __forceinline__ float ord2f(unsigned u) {
    unsigned b = (u & 0x80000000u) ? (u & 0x7fffffffu) : ~u;
    return __uint_as_float(b);
}

// ---------------- K1: u = att_vec @ W_edge, v = att_vec @ W_query (8 blocks) ----
__global__ void k_uv(const float* __restrict__ We, const float* __restrict__ Wq,
                     const float* __restrict__ av) {
    __shared__ float sa[H];
    __shared__ float ru[8][32], rv[8][32];
    int tx = threadIdx.x & 31, ty = threadIdx.x >> 5;
    sa[threadIdx.x] = av[threadIdx.x];
    __syncthreads();
    int col = blockIdx.x * 32 + tx;
    float u = 0.0f, v = 0.0f;
    #pragma unroll 4
    for (int j = ty; j < H; j += 8) {
        float a = sa[j];
        u = fmaf(a, We[j * H + col], u);
        v = fmaf(a, Wq[j * H + col], v);
    }
    ru[ty][tx] = u; rv[ty][tx] = v;
    __syncthreads();
    if (ty == 0) {
        float su = 0.0f, sv = 0.0f;
        #pragma unroll
        for (int r = 0; r < 8; r++) { su += ru[r][tx]; sv += rv[r][tx]; }
        d_u[col] = su; d_v[col] = sv;
    }
}

// ---------------- K1b: qatt[g] = question_tokens[g] . v   + scratch init ----------
__global__ void k_qatt(const float* __restrict__ qt) {
    int g = blockIdx.x, lane = threadIdx.x;
    float4 z = make_float4(0.f, 0.f, 0.f, 0.f);
    ((float4*)d_sumtok)[g * 64 + lane]      = z;
    ((float4*)d_sumtok)[g * 64 + 32 + lane] = z;
    if (lane == 0) { d_cnt[g] = 0; d_gmax[g] = 0u; }
    if (g == 0 && lane == 0) d_nrun = 0;
    const float4* q4 = (const float4*)(qt + g * H);
    const float4* v4 = (const float4*)d_v;
    float4 a = q4[lane], b = q4[lane + 32];
    float4 va = v4[lane], vb = v4[lane + 32];
    float s = a.x*va.x + a.y*va.y + a.z*va.z + a.w*va.w
            + b.x*vb.x + b.y*vb.y + b.z*vb.z + b.w*vb.w;
    #pragma unroll
    for (int o = 16; o; o >>= 1) s += __shfl_xor_sync(0xffffffffu, s, o);
    if (lane == 0) d_qatt[g] = s;
}

// ---------------- K2: main streaming pass (unroll-4, online run softmax) --------
struct RunState {
    int    cur_g;
    float4 cs0, cs1;
    int    cnt;
    float  rmax, rsum;
};

__device__ __forceinline__ void flush_run(const RunState& st, int lane) {
    float* sp = d_sumtok + st.cur_g * H;
    atomicAdd(sp + 4*lane + 0,       st.cs0.x);
    atomicAdd(sp + 4*lane + 1,       st.cs0.y);
    atomicAdd(sp + 4*lane + 2,       st.cs0.z);
    atomicAdd(sp + 4*lane + 3,       st.cs0.w);
    atomicAdd(sp + 128 + 4*lane + 0, st.cs1.x);
    atomicAdd(sp + 128 + 4*lane + 1, st.cs1.y);
    atomicAdd(sp + 128 + 4*lane + 2, st.cs1.z);
    atomicAdd(sp + 128 + 4*lane + 3, st.cs1.w);
    if (lane == 0) {
        atomicAdd(&d_cnt[st.cur_g], st.cnt);
        atomicMax(&d_gmax[st.cur_g], f2ord(st.rmax));
        int idx = atomicAdd(&d_nrun, 1);
        if (idx < RUN_CAP) {
            d_rg[idx] = st.cur_g; d_rm[idx] = st.rmax; d_rs[idx] = st.rsum;
        }
    }
}

__device__ __forceinline__ void reset_run(RunState& st, int g) {
    st.cur_g = g;
    st.cs0 = make_float4(0.f, 0.f, 0.f, 0.f);
    st.cs1 = make_float4(0.f, 0.f, 0.f, 0.f);
    st.cnt = 0; st.rmax = -3.0e38f; st.rsum = 0.0f;
}

// process one edge: s = warp-reduced dot, already has qatt added? (no — add here)
__device__ __forceinline__ void proc_edge(RunState& st, float4 a, float4 b,
                                          float s, int g, int m, int e, int lane) {
    if (g != st.cur_g) {
        flush_run(st, lane);
        reset_run(st, g);
    }
    st.cs0.x += a.x; st.cs0.y += a.y; st.cs0.z += a.z; st.cs0.w += a.w;
    st.cs1.x += b.x; st.cs1.y += b.y; st.cs1.z += b.z; st.cs1.w += b.w;
    float t = s + d_qatt[g];
    t = (t > 0.0f) ? t : 0.2f * t;
    if (m == 0) t += 0.5f;
    // warp-uniform branch (t identical across lanes)
    if (t > st.rmax) {
        st.rsum = st.rsum * __expf(st.rmax - t) + ((m == 0) ? 1.0f : 0.0f);
        st.rmax = t;
    } else if (m == 0) {
        st.rsum += __expf(t - st.rmax);
    }
    st.cnt++;
    if (lane == 0) d_att[e] = (m == 0) ? t : -1.0e38f;
}

__device__ __forceinline__ float dot8(float4 a, float4 b, float4 ua, float4 ub) {
    float s = a.x*ua.x; s = fmaf(a.y, ua.y, s); s = fmaf(a.z, ua.z, s);
    s = fmaf(a.w, ua.w, s); s = fmaf(b.x, ub.x, s); s = fmaf(b.y, ub.y, s);
    s = fmaf(b.z, ub.z, s); s = fmaf(b.w, ub.w, s);
    return s;
}

__global__ void __launch_bounds__(256, 3)
k_main(const float* __restrict__ et, const int* __restrict__ batch,
       const int* __restrict__ sel, int E, int epw) {
    int wid  = (blockIdx.x * blockDim.x + threadIdx.x) >> 5;
    int lane = threadIdx.x & 31;
    int start = wid * epw;
    if (start >= E) return;
    int end = min(E, start + epw);

    const float4* u4 = (const float4*)d_u;
    float4 ua = u4[lane], ub = u4[lane + 32];

    RunState st;
    reset_run(st, batch[start]);

    int e = start;
    for (; e + 3 < end; e += 4) {
        const float4* r0 = (const float4*)(et + (size_t)e * H);
        const float4* r1 = (const float4*)(et + (size_t)(e + 1) * H);
        const float4* r2 = (const float4*)(et + (size_t)(e + 2) * H);
        const float4* r3 = (const float4*)(et + (size_t)(e + 3) * H);
        float4 a0 = __ldcs(r0 + lane), b0 = __ldcs(r0 + lane + 32);
        float4 a1 = __ldcs(r1 + lane), b1 = __ldcs(r1 + lane + 32);
        float4 a2 = __ldcs(r2 + lane), b2 = __ldcs(r2 + lane + 32);
        float4 a3 = __ldcs(r3 + lane), b3 = __ldcs(r3 + lane + 32);
        int g0 = batch[e],     g1 = batch[e + 1];
        int g2 = batch[e + 2], g3 = batch[e + 3];
        int m0 = sel[e],       m1 = sel[e + 1];
        int m2 = sel[e + 2],   m3 = sel[e + 3];

        float s0 = dot8(a0, b0, ua, ub);
        float s1 = dot8(a1, b1, ua, ub);
        float s2 = dot8(a2, b2, ua, ub);
        float s3 = dot8(a3, b3, ua, ub);
        #pragma unroll
        for (int o = 16; o; o >>= 1) {   // 4 interleaved chains
            s0 += __shfl_xor_sync(0xffffffffu, s0, o);
            s1 += __shfl_xor_sync(0xffffffffu, s1, o);
            s2 += __shfl_xor_sync(0xffffffffu, s2, o);
            s3 += __shfl_xor_sync(0xffffffffu, s3, o);
        }
        proc_edge(st, a0, b0, s0, g0, m0, e,     lane);
        proc_edge(st, a1, b1, s1, g1, m1, e + 1, lane);
        proc_edge(st, a2, b2, s2, g2, m2, e + 2, lane);
        proc_edge(st, a3, b3, s3, g3, m3, e + 3, lane);
    }
    for (; e < end; e++) {   // tail (0-3 edges)
        const float4* r0 = (const float4*)(et + (size_t)e * H);
        float4 a0 = __ldcs(r0 + lane), b0 = __ldcs(r0 + lane + 32);
        int g0 = batch[e], m0 = sel[e];
        float s0 = dot8(a0, b0, ua, ub);
        #pragma unroll
        for (int o = 16; o; o >>= 1) s0 += __shfl_xor_sync(0xffffffffu, s0, o);
        proc_edge(st, a0, b0, s0, g0, m0, e, lane);
    }
    flush_run(st, lane);
}

// ---------------- K3: combine run records -> d_off[g] (block per graph) --------
__global__ void k_comb() {
    __shared__ float sred[2];
    int g = blockIdx.x;
    int t = threadIdx.x;                 // 64 threads
    int n = d_nrun; if (n > RUN_CAP) n = RUN_CAP;
    float m = ord2f(d_gmax[g]);
    float acc = 0.0f;
    for (int i = t; i < n; i += 64) {
        if (d_rg[i] == g) acc += d_rs[i] * __expf(d_rm[i] - m);
    }
    #pragma unroll
    for (int o = 16; o; o >>= 1) acc += __shfl_xor_sync(0xffffffffu, acc, o);
    if ((t & 31) == 0) sred[t >> 5] = acc;
    __syncthreads();
    if (t == 0)
        d_off[g] = m + logf(fmaxf(sred[0] + sred[1], FLT_EPSILON));
}

// ---------------- K4: edge_logits (vectorized x4) ----------------
__global__ void k_logits(const int* __restrict__ batch, float* __restrict__ out,
                         int E4) {
    int i = blockIdx.x * blockDim.x + threadIdx.x;
    if (i >= E4) return;
    int4   g = ((const int4*)batch)[i];
    float4 a = ((const float4*)d_att)[i];
    float4 r;
    r.x = fmaxf(a.x - d_off[g.x], LOGEPS);
    r.y = fmaxf(a.y - d_off[g.y], LOGEPS);
    r.z = fmaxf(a.z - d_off[g.z], LOGEPS);
    r.w = fmaxf(a.w - d_off[g.w], LOGEPS);
    ((float4*)out)[i] = r;
}
__global__ void k_logits_tail(const int* __restrict__ batch, float* __restrict__ out,
                              int start, int E) {
    int e = start + blockIdx.x * blockDim.x + threadIdx.x;
    if (e >= E) return;
    out[e] = fmaxf(d_att[e] - d_off[batch[e]], LOGEPS);
}

// ---------------- K5: pooled GEMM + stop head (GT graphs per block) ----------------
__global__ void __launch_bounds__(256)
k_head(const float* __restrict__ qt, const float* __restrict__ We,
       const float* __restrict__ lng, const float* __restrict__ lnb,
       const float* __restrict__ W1, const float* __restrict__ b1,
       const float* __restrict__ W2, const float* __restrict__ b2,
       float* __restrict__ out_stop, float* __restrict__ out_pool) {
    __shared__ float spool[GT][H];
    __shared__ float sxn[GT][H2];
    __shared__ float sred[8][GT];
    __shared__ float smu[GT], sinv[GT];
    int g0 = blockIdx.x * GT;
    int j = threadIdx.x;
    int w = j >> 5, lane = j & 31;

    #pragma unroll
    for (int g = 0; g < GT; g++) spool[g][j] = d_sumtok[(g0 + g) * H + j];
    __syncthreads();

    float pj[GT];
    #pragma unroll
    for (int g = 0; g < GT; g++) pj[g] = 0.0f;
    const float4* wr = (const float4*)(We + j * H);
    for (int k = 0; k < H / 4; k++) {
        float4 wv = wr[k];
        #pragma unroll
        for (int g = 0; g < GT; g++) {
            float4 x = ((const float4*)spool[g])[k];
            pj[g] = fmaf(wv.x, x.x, pj[g]); pj[g] = fmaf(wv.y, x.y, pj[g]);
            pj[g] = fmaf(wv.z, x.z, pj[g]); pj[g] = fmaf(wv.w, x.w, pj[g]);
        }
    }
    float x1[GT];
    #pragma unroll
    for (int g = 0; g < GT; g++) {
        float c = (float)max(d_cnt[g0 + g], 1);
        pj[g] /= c;
        out_pool[(g0 + g) * H + j] = pj[g];
        x1[g] = qt[(g0 + g) * H + j];
    }

    #pragma unroll
    for (int g = 0; g < GT; g++) {
        float v = pj[g] + x1[g];
        #pragma unroll
        for (int o = 16; o; o >>= 1) v += __shfl_xor_sync(0xffffffffu, v, o);
        if (lane == 0) sred[w][g] = v;
    }
    __syncthreads();
    if (j < GT) {
        float tot = 0.0f;
        #pragma unroll
        for (int r = 0; r < 8; r++) tot += sred[r][j];
        smu[j] = tot * (1.0f / 512.0f);
    }
    __syncthreads();
    #pragma unroll
    for (int g = 0; g < GT; g++) {
        float d0 = pj[g] - smu[g], d1 = x1[g] - smu[g];
        float v = d0 * d0 + d1 * d1;
        #pragma unroll
        for (int o = 16; o; o >>= 1) v += __shfl_xor_sync(0xffffffffu, v, o);
        if (lane == 0) sred[w][g] = v;
    }
    __syncthreads();
    if (j < GT) {
        float var = 0.0f;
        #pragma unroll
        for (int r = 0; r < 8; r++) var += sred[r][j];
        sinv[j] = rsqrtf(var * (1.0f / 512.0f) + 1e-5f);
    }
    __syncthreads();
    float g0v = lng[j], g1v = lng[H + j], b0v = lnb[j], b1v = lnb[H + j];
    #pragma unroll
    for (int g = 0; g < GT; g++) {
        sxn[g][j]     = (pj[g] - smu[g]) * sinv[g] * g0v + b0v;
        sxn[g][H + j] = (x1[g] - smu[g]) * sinv[g] * g1v + b1v;
    }
    __syncthreads();

    float hh[GT];
    float bb = b1[j];
    #pragma unroll
    for (int g = 0; g < GT; g++) hh[g] = bb;
    const float4* w1r = (const float4*)(W1 + j * H2);
    for (int k = 0; k < H2 / 4; k++) {
        float4 wv = w1r[k];
        #pragma unroll
        for (int g = 0; g < GT; g++) {
            float4 x = ((const float4*)sxn[g])[k];
            hh[g] = fmaf(wv.x, x.x, hh[g]); hh[g] = fmaf(wv.y, x.y, hh[g]);
            hh[g] = fmaf(wv.z, x.z, hh[g]); hh[g] = fmaf(wv.w, x.w, hh[g]);
        }
    }
    float w2j = W2[j];
    #pragma unroll
    for (int g = 0; g < GT; g++) {
        float h = hh[g];
        h = 0.5f * h * (1.0f + erff(h * 0.70710678118654752f));
        float v = h * w2j;
        #pragma unroll
        for (int o = 16; o; o >>= 1) v += __shfl_xor_sync(0xffffffffu, v, o);
        if (lane == 0) sred[w][g] = v;
    }
    __syncthreads();
    if (j < GT) {
        float st = 0.0f;
        #pragma unroll
        for (int r = 0; r < 8; r++) st += sred[r][j];
        out_stop[g0 + j] = st + b2[0];
    }
}

// ---------------- launch ----------------
extern "C" void kernel_launch(void* const* d_in, const int* in_sizes, int n_in,
                              void* d_out, int out_size) {
    const float* edge_tokens     = (const float*)d_in[0];
    const float* question_tokens = (const float*)d_in[1];
    const int*   edge_batch      = (const int*)d_in[2];
    const int*   selected_mask   = (const int*)d_in[3];
    const float* W_edge          = (const float*)d_in[4];
    const float* W_query         = (const float*)d_in[5];
    const float* att_vec         = (const float*)d_in[6];
    const float* ln_g            = (const float*)d_in[7];
    const float* ln_b            = (const float*)d_in[8];
    const float* W1              = (const float*)d_in[9];
    const float* b1              = (const float*)d_in[10];
    const float* W2              = (const float*)d_in[11];
    const float* b2              = (const float*)d_in[12];

    int E = in_sizes[2];
    float* out      = (float*)d_out;
    float* out_edge = out;             // [E]
    float* out_stop = out + E;         // [G]
    float* out_pool = out + E + G_;    // [G, H]

    k_uv<<<8, 256>>>(W_edge, W_query, att_vec);
    k_qatt<<<G_, 32>>>(question_tokens);
    // main pass: 3 blocks per SM (148*3 = 444), unroll-4
    {
        int blocks = 444, threads = 256;
        int warps = blocks * threads / 32;        // 3552
        int epw = (E + warps - 1) / warps;
        k_main<<<blocks, threads>>>(edge_tokens, edge_batch, selected_mask, E, epw);
    }
    k_comb<<<G_, 64>>>();
    {
        int E4 = E / 4;
        if (E4 > 0)
            k_logits<<<(E4 + 255) / 256, 256>>>(edge_batch, out_edge, E4);
        int rem = E - E4 * 4;
        if (rem > 0)
            k_logits_tail<<<(rem + 255) / 256, 256>>>(edge_batch, out_edge, E4 * 4, E);
    }
    k_head<<<G_ / GT, 256>>>(question_tokens, W_edge, ln_g, ln_b, W1, b1, W2, b2,
                             out_stop, out_pool);
}

// round 9
// speedup vs baseline: 1.0059x; 1.0059x over previous
#include <cuda_runtime.h>
#include <math.h>
#include <float.h>

#define H 256
#define G_ 256
#define H2 512
#define E_MAX 524288
#define GT 8                            // graphs per block in k_head
#define RUN_CAP 8192
#define LOGEPS -15.942385152878742f     // logf(FLT_EPSILON)

// ---------------- scratch (static device globals; no allocation) ----------------
__device__ float    d_att[E_MAX];      // att score (candidates); -1e38 for selected
__device__ float    d_sumtok[G_ * H];  // segment sum of edge_tokens
__device__ int      d_cnt[G_];         // edges per graph
__device__ unsigned d_gmax[G_];        // ordered-uint encoded segment max
__device__ float    d_off[G_];         // gmax + log(gsum) per graph
__device__ float    d_u[H];            // att_vec @ W_edge
__device__ float    d_v[H];            // att_vec @ W_query
__device__ float    d_qatt[G_];        // question_tokens @ v
__device__ int      d_nrun;            // run record counter
__device__ float4   d_rec[RUN_CAP];    // packed run records {g_as_float, rmax, rsum, 0}

__device__ __forceinline__ unsigned f2ord(float f) {
    unsigned b = __float_as_uint(f);
    return (b & 0x80000000u) ? ~b : (b | 0x80000000u);
}
__device__ __forceinline__ float ord2f(unsigned u) {
    unsigned b = (u & 0x80000000u) ? (u & 0x7fffffffu) : ~u;
    return __uint_as_float(b);
}

// ---------------- K1: u = att_vec @ W_edge, v = att_vec @ W_query (8 blocks) ----
__global__ void k_uv(const float* __restrict__ We, const float* __restrict__ Wq,
                     const float* __restrict__ av) {
    __shared__ float sa[H];
    __shared__ float ru[8][32], rv[8][32];
    int tx = threadIdx.x & 31, ty = threadIdx.x >> 5;
    sa[threadIdx.x] = av[threadIdx.x];
    __syncthreads();
    int col = blockIdx.x * 32 + tx;
    float u = 0.0f, v = 0.0f;
    #pragma unroll 4
    for (int j = ty; j < H; j += 8) {
        float a = sa[j];
        u = fmaf(a, We[j * H + col], u);
        v = fmaf(a, Wq[j * H + col], v);
    }
    ru[ty][tx] = u; rv[ty][tx] = v;
    __syncthreads();
    if (ty == 0) {
        float su = 0.0f, sv = 0.0f;
        #pragma unroll
        for (int r = 0; r < 8; r++) { su += ru[r][tx]; sv += rv[r][tx]; }
        d_u[col] = su; d_v[col] = sv;
    }
}

// ---------------- K1b: qatt[g] = question_tokens[g] . v   + scratch init ----------
__global__ void k_qatt(const float* __restrict__ qt) {
    int g = blockIdx.x, lane = threadIdx.x;
    float4 z = make_float4(0.f, 0.f, 0.f, 0.f);
    ((float4*)d_sumtok)[g * 64 + lane]      = z;
    ((float4*)d_sumtok)[g * 64 + 32 + lane] = z;
    if (lane == 0) { d_cnt[g] = 0; d_gmax[g] = 0u; }
    if (g == 0 && lane == 0) d_nrun = 0;
    const float4* q4 = (const float4*)(qt + g * H);
    const float4* v4 = (const float4*)d_v;
    float4 a = q4[lane], b = q4[lane + 32];
    float4 va = v4[lane], vb = v4[lane + 32];
    float s = a.x*va.x + a.y*va.y + a.z*va.z + a.w*va.w
            + b.x*vb.x + b.y*vb.y + b.z*vb.z + b.w*vb.w;
    #pragma unroll
    for (int o = 16; o; o >>= 1) s += __shfl_xor_sync(0xffffffffu, s, o);
    if (lane == 0) d_qatt[g] = s;
}

// ---------------- K2: main streaming pass (unroll-4, online run softmax) --------
struct RunState {
    int    cur_g;
    float4 cs0, cs1;
    int    cnt;
    float  rmax, rsum;
};

__device__ __forceinline__ void flush_run(const RunState& st, int lane) {
    float* sp = d_sumtok + st.cur_g * H;
    atomicAdd(sp + 4*lane + 0,       st.cs0.x);
    atomicAdd(sp + 4*lane + 1,       st.cs0.y);
    atomicAdd(sp + 4*lane + 2,       st.cs0.z);
    atomicAdd(sp + 4*lane + 3,       st.cs0.w);
    atomicAdd(sp + 128 + 4*lane + 0, st.cs1.x);
    atomicAdd(sp + 128 + 4*lane + 1, st.cs1.y);
    atomicAdd(sp + 128 + 4*lane + 2, st.cs1.z);
    atomicAdd(sp + 128 + 4*lane + 3, st.cs1.w);
    if (lane == 0) {
        atomicAdd(&d_cnt[st.cur_g], st.cnt);
        atomicMax(&d_gmax[st.cur_g], f2ord(st.rmax));
        int idx = atomicAdd(&d_nrun, 1);
        if (idx < RUN_CAP) {
            d_rec[idx] = make_float4(__int_as_float(st.cur_g), st.rmax, st.rsum, 0.0f);
        }
    }
}

__device__ __forceinline__ void reset_run(RunState& st, int g) {
    st.cur_g = g;
    st.cs0 = make_float4(0.f, 0.f, 0.f, 0.f);
    st.cs1 = make_float4(0.f, 0.f, 0.f, 0.f);
    st.cnt = 0; st.rmax = -3.0e38f; st.rsum = 0.0f;
}

__device__ __forceinline__ void proc_edge(RunState& st, float4 a, float4 b,
                                          float s, int g, int m, int e, int lane) {
    if (g != st.cur_g) {
        flush_run(st, lane);
        reset_run(st, g);
    }
    st.cs0.x += a.x; st.cs0.y += a.y; st.cs0.z += a.z; st.cs0.w += a.w;
    st.cs1.x += b.x; st.cs1.y += b.y; st.cs1.z += b.z; st.cs1.w += b.w;
    float t = s + d_qatt[g];
    t = (t > 0.0f) ? t : 0.2f * t;
    if (m == 0) t += 0.5f;
    // warp-uniform branch (t identical across lanes)
    if (t > st.rmax) {
        st.rsum = st.rsum * __expf(st.rmax - t) + ((m == 0) ? 1.0f : 0.0f);
        st.rmax = t;
    } else if (m == 0) {
        st.rsum += __expf(t - st.rmax);
    }
    st.cnt++;
    if (lane == 0) d_att[e] = (m == 0) ? t : -1.0e38f;
}

__device__ __forceinline__ float dot8(float4 a, float4 b, float4 ua, float4 ub) {
    float s = a.x*ua.x; s = fmaf(a.y, ua.y, s); s = fmaf(a.z, ua.z, s);
    s = fmaf(a.w, ua.w, s); s = fmaf(b.x, ub.x, s); s = fmaf(b.y, ub.y, s);
    s = fmaf(b.z, ub.z, s); s = fmaf(b.w, ub.w, s);
    return s;
}

__global__ void __launch_bounds__(256, 3)
k_main(const float* __restrict__ et, const int* __restrict__ batch,
       const int* __restrict__ sel, int E, int epw) {
    int wid  = (blockIdx.x * blockDim.x + threadIdx.x) >> 5;
    int lane = threadIdx.x & 31;
    int start = wid * epw;
    if (start >= E) return;
    int end = min(E, start + epw);

    const float4* u4 = (const float4*)d_u;
    float4 ua = u4[lane], ub = u4[lane + 32];

    RunState st;
    reset_run(st, batch[start]);

    int e = start;
    for (; e + 3 < end; e += 4) {
        const float4* r0 = (const float4*)(et + (size_t)e * H);
        const float4* r1 = (const float4*)(et + (size_t)(e + 1) * H);
        const float4* r2 = (const float4*)(et + (size_t)(e + 2) * H);
        const float4* r3 = (const float4*)(et + (size_t)(e + 3) * H);
        float4 a0 = __ldcs(r0 + lane), b0 = __ldcs(r0 + lane + 32);
        float4 a1 = __ldcs(r1 + lane), b1 = __ldcs(r1 + lane + 32);
        float4 a2 = __ldcs(r2 + lane), b2 = __ldcs(r2 + lane + 32);
        float4 a3 = __ldcs(r3 + lane), b3 = __ldcs(r3 + lane + 32);
        int g0 = batch[e],     g1 = batch[e + 1];
        int g2 = batch[e + 2], g3 = batch[e + 3];
        int m0 = sel[e],       m1 = sel[e + 1];
        int m2 = sel[e + 2],   m3 = sel[e + 3];

        float s0 = dot8(a0, b0, ua, ub);
        float s1 = dot8(a1, b1, ua, ub);
        float s2 = dot8(a2, b2, ua, ub);
        float s3 = dot8(a3, b3, ua, ub);
        #pragma unroll
        for (int o = 16; o; o >>= 1) {   // 4 interleaved chains
            s0 += __shfl_xor_sync(0xffffffffu, s0, o);
            s1 += __shfl_xor_sync(0xffffffffu, s1, o);
            s2 += __shfl_xor_sync(0xffffffffu, s2, o);
            s3 += __shfl_xor_sync(0xffffffffu, s3, o);
        }
        proc_edge(st, a0, b0, s0, g0, m0, e,     lane);
        proc_edge(st, a1, b1, s1, g1, m1, e + 1, lane);
        proc_edge(st, a2, b2, s2, g2, m2, e + 2, lane);
        proc_edge(st, a3, b3, s3, g3, m3, e + 3, lane);
    }
    for (; e < end; e++) {   // tail (0-3 edges)
        const float4* r0 = (const float4*)(et + (size_t)e * H);
        float4 a0 = __ldcs(r0 + lane), b0 = __ldcs(r0 + lane + 32);
        int g0 = batch[e], m0 = sel[e];
        float s0 = dot8(a0, b0, ua, ub);
        #pragma unroll
        for (int o = 16; o; o >>= 1) s0 += __shfl_xor_sync(0xffffffffu, s0, o);
        proc_edge(st, a0, b0, s0, g0, m0, e, lane);
    }
    flush_run(st, lane);
}

// ---------------- K3: combine run records -> d_off[g] (block per graph, 256 thr) --
__global__ void __launch_bounds__(256)
k_comb() {
    __shared__ float sred[8];
    int g = blockIdx.x;
    int t = threadIdx.x;
    int w = t >> 5, lane = t & 31;
    int n = d_nrun; if (n > RUN_CAP) n = RUN_CAP;
    float m = ord2f(d_gmax[g]);
    float acc = 0.0f;
    for (int i = t; i < n; i += 256) {
        float4 r = d_rec[i];                       // one coalesced 16B load
        if (__float_as_int(r.x) == g) acc += r.z * __expf(r.y - m);
    }
    #pragma unroll
    for (int o = 16; o; o >>= 1) acc += __shfl_xor_sync(0xffffffffu, acc, o);
    if (lane == 0) sred[w] = acc;
    __syncthreads();
    if (t < 32) {
        float v = (t < 8) ? sred[t] : 0.0f;
        #pragma unroll
        for (int o = 4; o; o >>= 1) v += __shfl_xor_sync(0xffffffffu, v, o);
        if (t == 0) d_off[g] = m + logf(fmaxf(v, FLT_EPSILON));
    }
}

// ---------------- K4: edge_logits (vectorized x4) ----------------
__global__ void k_logits(const int* __restrict__ batch, float* __restrict__ out,
                         int E4) {
    int i = blockIdx.x * blockDim.x + threadIdx.x;
    if (i >= E4) return;
    int4   g = ((const int4*)batch)[i];
    float4 a = ((const float4*)d_att)[i];
    float4 r;
    r.x = fmaxf(a.x - d_off[g.x], LOGEPS);
    r.y = fmaxf(a.y - d_off[g.y], LOGEPS);
    r.z = fmaxf(a.z - d_off[g.z], LOGEPS);
    r.w = fmaxf(a.w - d_off[g.w], LOGEPS);
    ((float4*)out)[i] = r;
}
__global__ void k_logits_tail(const int* __restrict__ batch, float* __restrict__ out,
                              int start, int E) {
    int e = start + blockIdx.x * blockDim.x + threadIdx.x;
    if (e >= E) return;
    out[e] = fmaxf(d_att[e] - d_off[batch[e]], LOGEPS);
}

// ---------------- K5: pooled GEMM + stop head (GT graphs per block) ----------------
__global__ void __launch_bounds__(256)
k_head(const float* __restrict__ qt, const float* __restrict__ We,
       const float* __restrict__ lng, const float* __restrict__ lnb,
       const float* __restrict__ W1, const float* __restrict__ b1,
       const float* __restrict__ W2, const float* __restrict__ b2,
       float* __restrict__ out_stop, float* __restrict__ out_pool) {
    __shared__ float spool[GT][H];
    __shared__ float sxn[GT][H2];
    __shared__ float sred[8][GT];
    __shared__ float smu[GT], sinv[GT];
    int g0 = blockIdx.x * GT;
    int j = threadIdx.x;
    int w = j >> 5, lane = j & 31;

    #pragma unroll
    for (int g = 0; g < GT; g++) spool[g][j] = d_sumtok[(g0 + g) * H + j];
    __syncthreads();

    float pj[GT];
    #pragma unroll
    for (int g = 0; g < GT; g++) pj[g] = 0.0f;
    const float4* wr = (const float4*)(We + j * H);
    for (int k = 0; k < H / 4; k++) {
        float4 wv = wr[k];
        #pragma unroll
        for (int g = 0; g < GT; g++) {
            float4 x = ((const float4*)spool[g])[k];
            pj[g] = fmaf(wv.x, x.x, pj[g]); pj[g] = fmaf(wv.y, x.y, pj[g]);
            pj[g] = fmaf(wv.z, x.z, pj[g]); pj[g] = fmaf(wv.w, x.w, pj[g]);
        }
    }
    float x1[GT];
    #pragma unroll
    for (int g = 0; g < GT; g++) {
        float c = (float)max(d_cnt[g0 + g], 1);
        pj[g] /= c;
        out_pool[(g0 + g) * H + j] = pj[g];
        x1[g] = qt[(g0 + g) * H + j];
    }

    #pragma unroll
    for (int g = 0; g < GT; g++) {
        float v = pj[g] + x1[g];
        #pragma unroll
        for (int o = 16; o; o >>= 1) v += __shfl_xor_sync(0xffffffffu, v, o);
        if (lane == 0) sred[w][g] = v;
    }
    __syncthreads();
    if (j < GT) {
        float tot = 0.0f;
        #pragma unroll
        for (int r = 0; r < 8; r++) tot += sred[r][j];
        smu[j] = tot * (1.0f / 512.0f);
    }
    __syncthreads();
    #pragma unroll
    for (int g = 0; g < GT; g++) {
        float d0 = pj[g] - smu[g], d1 = x1[g] - smu[g];
        float v = d0 * d0 + d1 * d1;
        #pragma unroll
        for (int o = 16; o; o >>= 1) v += __shfl_xor_sync(0xffffffffu, v, o);
        if (lane == 0) sred[w][g] = v;
    }
    __syncthreads();
    if (j < GT) {
        float var = 0.0f;
        #pragma unroll
        for (int r = 0; r < 8; r++) var += sred[r][j];
        sinv[j] = rsqrtf(var * (1.0f / 512.0f) + 1e-5f);
    }
    __syncthreads();
    float g0v = lng[j], g1v = lng[H + j], b0v = lnb[j], b1v = lnb[H + j];
    #pragma unroll
    for (int g = 0; g < GT; g++) {
        sxn[g][j]     = (pj[g] - smu[g]) * sinv[g] * g0v + b0v;
        sxn[g][H + j] = (x1[g] - smu[g]) * sinv[g] * g1v + b1v;
    }
    __syncthreads();

    float hh[GT];
    float bb = b1[j];
    #pragma unroll
    for (int g = 0; g < GT; g++) hh[g] = bb;
    const float4* w1r = (const float4*)(W1 + j * H2);
    for (int k = 0; k < H2 / 4; k++) {
        float4 wv = w1r[k];
        #pragma unroll
        for (int g = 0; g < GT; g++) {
            float4 x = ((const float4*)sxn[g])[k];
            hh[g] = fmaf(wv.x, x.x, hh[g]); hh[g] = fmaf(wv.y, x.y, hh[g]);
            hh[g] = fmaf(wv.z, x.z, hh[g]); hh[g] = fmaf(wv.w, x.w, hh[g]);
        }
    }
    float w2j = W2[j];
    #pragma unroll
    for (int g = 0; g < GT; g++) {
        float h = hh[g];
        h = 0.5f * h * (1.0f + erff(h * 0.70710678118654752f));
        float v = h * w2j;
        #pragma unroll
        for (int o = 16; o; o >>= 1) v += __shfl_xor_sync(0xffffffffu, v, o);
        if (lane == 0) sred[w][g] = v;
    }
    __syncthreads();
    if (j < GT) {
        float st = 0.0f;
        #pragma unroll
        for (int r = 0; r < 8; r++) st += sred[r][j];
        out_stop[g0 + j] = st + b2[0];
    }
}

// ---------------- launch ----------------
extern "C" void kernel_launch(void* const* d_in, const int* in_sizes, int n_in,
                              void* d_out, int out_size) {
    const float* edge_tokens     = (const float*)d_in[0];
    const float* question_tokens = (const float*)d_in[1];
    const int*   edge_batch      = (const int*)d_in[2];
    const int*   selected_mask   = (const int*)d_in[3];
    const float* W_edge          = (const float*)d_in[4];
    const float* W_query         = (const float*)d_in[5];
    const float* att_vec         = (const float*)d_in[6];
    const float* ln_g            = (const float*)d_in[7];
    const float* ln_b            = (const float*)d_in[8];
    const float* W1              = (const float*)d_in[9];
    const float* b1              = (const float*)d_in[10];
    const float* W2              = (const float*)d_in[11];
    const float* b2              = (const float*)d_in[12];

    int E = in_sizes[2];
    float* out      = (float*)d_out;
    float* out_edge = out;             // [E]
    float* out_stop = out + E;         // [G]
    float* out_pool = out + E + G_;    // [G, H]

    k_uv<<<8, 256>>>(W_edge, W_query, att_vec);
    k_qatt<<<G_, 32>>>(question_tokens);
    // main pass: 3 blocks per SM (148*3 = 444), unroll-4
    {
        int blocks = 444, threads = 256;
        int warps = blocks * threads / 32;        // 3552
        int epw = (E + warps - 1) / warps;
        k_main<<<blocks, threads>>>(edge_tokens, edge_batch, selected_mask, E, epw);
    }
    k_comb<<<G_, 256>>>();
    {
        int E4 = E / 4;
        if (E4 > 0)
            k_logits<<<(E4 + 255) / 256, 256>>>(edge_batch, out_edge, E4);
        int rem = E - E4 * 4;
        if (rem > 0)
            k_logits_tail<<<(rem + 255) / 256, 256>>>(edge_batch, out_edge, E4 * 4, E);
    }
    k_head<<<G_ / GT, 256>>>(question_tokens, W_edge, ln_g, ln_b, W1, b1, W2, b2,
                             out_stop, out_pool);
}

// round 10
// speedup vs baseline: 1.0285x; 1.0224x over previous
#include <cuda_runtime.h>
#include <math.h>
#include <float.h>

#define H 256
#define G_ 256
#define H2 512
#define E_MAX 524288
#define GT 8                            // graphs per block in k_head
#define RUN_CAP 8192
#define NSLICE 8                        // record slices in k_comb
#define LOGEPS -15.942385152878742f     // logf(FLT_EPSILON)

// ---------------- scratch (static device globals; no allocation) ----------------
__device__ float    d_att[E_MAX];      // att score (candidates); -1e38 for selected
__device__ float    d_sumtok[G_ * H];  // segment sum of edge_tokens
__device__ int      d_cnt[G_];         // edges per graph
__device__ unsigned d_gmax[G_];        // ordered-uint encoded segment max
__device__ float    d_gsum[G_];        // per-graph exp-sum (rebased to gmax)
__device__ float    d_off[G_];         // gmax + log(gsum)
__device__ float    d_u[H];            // att_vec @ W_edge
__device__ float    d_v[H];            // att_vec @ W_query
__device__ float    d_qatt[G_];        // question_tokens @ v
__device__ int      d_nrun;            // run record counter
__device__ float4   d_rec[RUN_CAP];    // packed run records {g_as_float, rmax, rsum, 0}

__device__ __forceinline__ unsigned f2ord(float f) {
    unsigned b = __float_as_uint(f);
    return (b & 0x80000000u) ? ~b : (b | 0x80000000u);
}
__device__ __forceinline__ float ord2f(unsigned u) {
    unsigned b = (u & 0x80000000u) ? (u & 0x7fffffffu) : ~u;
    return __uint_as_float(b);
}

// ---------------- K1: u = att_vec @ W_edge, v = att_vec @ W_query (8 blocks) ----
__global__ void k_uv(const float* __restrict__ We, const float* __restrict__ Wq,
                     const float* __restrict__ av) {
    __shared__ float sa[H];
    __shared__ float ru[8][32], rv[8][32];
    int tx = threadIdx.x & 31, ty = threadIdx.x >> 5;
    sa[threadIdx.x] = av[threadIdx.x];
    __syncthreads();
    int col = blockIdx.x * 32 + tx;
    float u = 0.0f, v = 0.0f;
    #pragma unroll 4
    for (int j = ty; j < H; j += 8) {
        float a = sa[j];
        u = fmaf(a, We[j * H + col], u);
        v = fmaf(a, Wq[j * H + col], v);
    }
    ru[ty][tx] = u; rv[ty][tx] = v;
    __syncthreads();
    if (ty == 0) {
        float su = 0.0f, sv = 0.0f;
        #pragma unroll
        for (int r = 0; r < 8; r++) { su += ru[r][tx]; sv += rv[r][tx]; }
        d_u[col] = su; d_v[col] = sv;
    }
}

// ---------------- K1b: qatt[g] = question_tokens[g] . v   + scratch init ----------
__global__ void k_qatt(const float* __restrict__ qt) {
    int g = blockIdx.x, lane = threadIdx.x;
    float4 z = make_float4(0.f, 0.f, 0.f, 0.f);
    ((float4*)d_sumtok)[g * 64 + lane]      = z;
    ((float4*)d_sumtok)[g * 64 + 32 + lane] = z;
    if (lane == 0) { d_cnt[g] = 0; d_gmax[g] = 0u; d_gsum[g] = 0.0f; }
    if (g == 0 && lane == 0) d_nrun = 0;
    const float4* q4 = (const float4*)(qt + g * H);
    const float4* v4 = (const float4*)d_v;
    float4 a = q4[lane], b = q4[lane + 32];
    float4 va = v4[lane], vb = v4[lane + 32];
    float s = a.x*va.x + a.y*va.y + a.z*va.z + a.w*va.w
            + b.x*vb.x + b.y*vb.y + b.z*vb.z + b.w*vb.w;
    #pragma unroll
    for (int o = 16; o; o >>= 1) s += __shfl_xor_sync(0xffffffffu, s, o);
    if (lane == 0) d_qatt[g] = s;
}

// ---------------- K2: main streaming pass (unroll-2, occ-4, online softmax) -----
struct RunState {
    int    cur_g;
    float4 cs0, cs1;
    int    cnt;
    float  rmax, rsum;
};

__device__ __forceinline__ void flush_run(const RunState& st, int lane) {
    float* sp = d_sumtok + st.cur_g * H;
    atomicAdd(sp + 4*lane + 0,       st.cs0.x);
    atomicAdd(sp + 4*lane + 1,       st.cs0.y);
    atomicAdd(sp + 4*lane + 2,       st.cs0.z);
    atomicAdd(sp + 4*lane + 3,       st.cs0.w);
    atomicAdd(sp + 128 + 4*lane + 0, st.cs1.x);
    atomicAdd(sp + 128 + 4*lane + 1, st.cs1.y);
    atomicAdd(sp + 128 + 4*lane + 2, st.cs1.z);
    atomicAdd(sp + 128 + 4*lane + 3, st.cs1.w);
    if (lane == 0) {
        atomicAdd(&d_cnt[st.cur_g], st.cnt);
        atomicMax(&d_gmax[st.cur_g], f2ord(st.rmax));
        int idx = atomicAdd(&d_nrun, 1);
        if (idx < RUN_CAP) {
            d_rec[idx] = make_float4(__int_as_float(st.cur_g), st.rmax, st.rsum, 0.0f);
        }
    }
}

__device__ __forceinline__ void reset_run(RunState& st, int g) {
    st.cur_g = g;
    st.cs0 = make_float4(0.f, 0.f, 0.f, 0.f);
    st.cs1 = make_float4(0.f, 0.f, 0.f, 0.f);
    st.cnt = 0; st.rmax = -3.0e38f; st.rsum = 0.0f;
}

__device__ __forceinline__ void proc_edge(RunState& st, float4 a, float4 b,
                                          float s, int g, int m, int e, int lane) {
    if (g != st.cur_g) {
        flush_run(st, lane);
        reset_run(st, g);
    }
    st.cs0.x += a.x; st.cs0.y += a.y; st.cs0.z += a.z; st.cs0.w += a.w;
    st.cs1.x += b.x; st.cs1.y += b.y; st.cs1.z += b.z; st.cs1.w += b.w;
    float t = s + d_qatt[g];
    t = (t > 0.0f) ? t : 0.2f * t;
    if (m == 0) t += 0.5f;
    // warp-uniform branch (t identical across lanes)
    if (t > st.rmax) {
        st.rsum = st.rsum * __expf(st.rmax - t) + ((m == 0) ? 1.0f : 0.0f);
        st.rmax = t;
    } else if (m == 0) {
        st.rsum += __expf(t - st.rmax);
    }
    st.cnt++;
    if (lane == 0) d_att[e] = (m == 0) ? t : -1.0e38f;
}

__device__ __forceinline__ float dot8(float4 a, float4 b, float4 ua, float4 ub) {
    float s = a.x*ua.x; s = fmaf(a.y, ua.y, s); s = fmaf(a.z, ua.z, s);
    s = fmaf(a.w, ua.w, s); s = fmaf(b.x, ub.x, s); s = fmaf(b.y, ub.y, s);
    s = fmaf(b.z, ub.z, s); s = fmaf(b.w, ub.w, s);
    return s;
}

__global__ void __launch_bounds__(256, 4)
k_main(const float* __restrict__ et, const int* __restrict__ batch,
       const int* __restrict__ sel, int E, int epw) {
    int wid  = (blockIdx.x * blockDim.x + threadIdx.x) >> 5;
    int lane = threadIdx.x & 31;
    int start = wid * epw;
    if (start >= E) return;
    int end = min(E, start + epw);

    const float4* u4 = (const float4*)d_u;
    float4 ua = u4[lane], ub = u4[lane + 32];

    RunState st;
    reset_run(st, batch[start]);

    int e = start;
    for (; e + 1 < end; e += 2) {
        const float4* r0 = (const float4*)(et + (size_t)e * H);
        const float4* r1 = (const float4*)(et + (size_t)(e + 1) * H);
        float4 a0 = __ldcs(r0 + lane), b0 = __ldcs(r0 + lane + 32);
        float4 a1 = __ldcs(r1 + lane), b1 = __ldcs(r1 + lane + 32);
        int g0 = batch[e], g1 = batch[e + 1];
        int m0 = sel[e],   m1 = sel[e + 1];

        float s0 = dot8(a0, b0, ua, ub);
        float s1 = dot8(a1, b1, ua, ub);
        #pragma unroll
        for (int o = 16; o; o >>= 1) {
            s0 += __shfl_xor_sync(0xffffffffu, s0, o);
            s1 += __shfl_xor_sync(0xffffffffu, s1, o);
        }
        proc_edge(st, a0, b0, s0, g0, m0, e,     lane);
        proc_edge(st, a1, b1, s1, g1, m1, e + 1, lane);
    }
    if (e < end) {   // tail edge
        const float4* r0 = (const float4*)(et + (size_t)e * H);
        float4 a0 = __ldcs(r0 + lane), b0 = __ldcs(r0 + lane + 32);
        int g0 = batch[e], m0 = sel[e];
        float s0 = dot8(a0, b0, ua, ub);
        #pragma unroll
        for (int o = 16; o; o >>= 1) s0 += __shfl_xor_sync(0xffffffffu, s0, o);
        proc_edge(st, a0, b0, s0, g0, m0, e, lane);
    }
    flush_run(st, lane);
}

// ---------------- K3: combine run records -> d_gsum[g]  (graph x slice grid) ----
__global__ void __launch_bounds__(256)
k_comb() {
    __shared__ float sred[8];
    int g = blockIdx.x;
    int slice = blockIdx.y;
    int t = threadIdx.x;
    int w = t >> 5, lane = t & 31;
    int n = d_nrun; if (n > RUN_CAP) n = RUN_CAP;
    int per = (n + NSLICE - 1) / NSLICE;
    int lo = slice * per;
    int hi = min(n, lo + per);
    float m = ord2f(d_gmax[g]);
    float acc = 0.0f;
    for (int i = lo + t; i < hi; i += 256) {
        float4 r = d_rec[i];                       // one coalesced 16B load
        if (__float_as_int(r.x) == g) acc += r.z * __expf(r.y - m);
    }
    #pragma unroll
    for (int o = 16; o; o >>= 1) acc += __shfl_xor_sync(0xffffffffu, acc, o);
    if (lane == 0) sred[w] = acc;
    __syncthreads();
    if (t < 32) {
        float v = (t < 8) ? sred[t] : 0.0f;
        #pragma unroll
        for (int o = 4; o; o >>= 1) v += __shfl_xor_sync(0xffffffffu, v, o);
        if (t == 0 && v != 0.0f) atomicAdd(&d_gsum[g], v);
    }
}

// ---------------- K3b: finalize d_off ----------------
__global__ void k_fin() {
    int g = threadIdx.x;
    d_off[g] = ord2f(d_gmax[g]) + logf(fmaxf(d_gsum[g], FLT_EPSILON));
}

// ---------------- K4: edge_logits (vectorized x4) ----------------
__global__ void k_logits(const int* __restrict__ batch, float* __restrict__ out,
                         int E4) {
    int i = blockIdx.x * blockDim.x + threadIdx.x;
    if (i >= E4) return;
    int4   g = ((const int4*)batch)[i];
    float4 a = ((const float4*)d_att)[i];
    float4 r;
    r.x = fmaxf(a.x - d_off[g.x], LOGEPS);
    r.y = fmaxf(a.y - d_off[g.y], LOGEPS);
    r.z = fmaxf(a.z - d_off[g.z], LOGEPS);
    r.w = fmaxf(a.w - d_off[g.w], LOGEPS);
    ((float4*)out)[i] = r;
}
__global__ void k_logits_tail(const int* __restrict__ batch, float* __restrict__ out,
                              int start, int E) {
    int e = start + blockIdx.x * blockDim.x + threadIdx.x;
    if (e >= E) return;
    out[e] = fmaxf(d_att[e] - d_off[batch[e]], LOGEPS);
}

// ---------------- K5: pooled GEMM + stop head (GT graphs per block) ----------------
__global__ void __launch_bounds__(256)
k_head(const float* __restrict__ qt, const float* __restrict__ We,
       const float* __restrict__ lng, const float* __restrict__ lnb,
       const float* __restrict__ W1, const float* __restrict__ b1,
       const float* __restrict__ W2, const float* __restrict__ b2,
       float* __restrict__ out_stop, float* __restrict__ out_pool) {
    __shared__ float spool[GT][H];
    __shared__ float sxn[GT][H2];
    __shared__ float sred[8][GT];
    __shared__ float smu[GT], sinv[GT];
    int g0 = blockIdx.x * GT;
    int j = threadIdx.x;
    int w = j >> 5, lane = j & 31;

    #pragma unroll
    for (int g = 0; g < GT; g++) spool[g][j] = d_sumtok[(g0 + g) * H + j];
    __syncthreads();

    float pj[GT];
    #pragma unroll
    for (int g = 0; g < GT; g++) pj[g] = 0.0f;
    const float4* wr = (const float4*)(We + j * H);
    for (int k = 0; k < H / 4; k++) {
        float4 wv = wr[k];
        #pragma unroll
        for (int g = 0; g < GT; g++) {
            float4 x = ((const float4*)spool[g])[k];
            pj[g] = fmaf(wv.x, x.x, pj[g]); pj[g] = fmaf(wv.y, x.y, pj[g]);
            pj[g] = fmaf(wv.z, x.z, pj[g]); pj[g] = fmaf(wv.w, x.w, pj[g]);
        }
    }
    float x1[GT];
    #pragma unroll
    for (int g = 0; g < GT; g++) {
        float c = (float)max(d_cnt[g0 + g], 1);
        pj[g] /= c;
        out_pool[(g0 + g) * H + j] = pj[g];
        x1[g] = qt[(g0 + g) * H + j];
    }

    #pragma unroll
    for (int g = 0; g < GT; g++) {
        float v = pj[g] + x1[g];
        #pragma unroll
        for (int o = 16; o; o >>= 1) v += __shfl_xor_sync(0xffffffffu, v, o);
        if (lane == 0) sred[w][g] = v;
    }
    __syncthreads();
    if (j < GT) {
        float tot = 0.0f;
        #pragma unroll
        for (int r = 0; r < 8; r++) tot += sred[r][j];
        smu[j] = tot * (1.0f / 512.0f);
    }
    __syncthreads();
    #pragma unroll
    for (int g = 0; g < GT; g++) {
        float d0 = pj[g] - smu[g], d1 = x1[g] - smu[g];
        float v = d0 * d0 + d1 * d1;
        #pragma unroll
        for (int o = 16; o; o >>= 1) v += __shfl_xor_sync(0xffffffffu, v, o);
        if (lane == 0) sred[w][g] = v;
    }
    __syncthreads();
    if (j < GT) {
        float var = 0.0f;
        #pragma unroll
        for (int r = 0; r < 8; r++) var += sred[r][j];
        sinv[j] = rsqrtf(var * (1.0f / 512.0f) + 1e-5f);
    }
    __syncthreads();
    float g0v = lng[j], g1v = lng[H + j], b0v = lnb[j], b1v = lnb[H + j];
    #pragma unroll
    for (int g = 0; g < GT; g++) {
        sxn[g][j]     = (pj[g] - smu[g]) * sinv[g] * g0v + b0v;
        sxn[g][H + j] = (x1[g] - smu[g]) * sinv[g] * g1v + b1v;
    }
    __syncthreads();

    float hh[GT];
    float bb = b1[j];
    #pragma unroll
    for (int g = 0; g < GT; g++) hh[g] = bb;
    const float4* w1r = (const float4*)(W1 + j * H2);
    for (int k = 0; k < H2 / 4; k++) {
        float4 wv = w1r[k];
        #pragma unroll
        for (int g = 0; g < GT; g++) {
            float4 x = ((const float4*)sxn[g])[k];
            hh[g] = fmaf(wv.x, x.x, hh[g]); hh[g] = fmaf(wv.y, x.y, hh[g]);
            hh[g] = fmaf(wv.z, x.z, hh[g]); hh[g] = fmaf(wv.w, x.w, hh[g]);
        }
    }
    float w2j = W2[j];
    #pragma unroll
    for (int g = 0; g < GT; g++) {
        float h = hh[g];
        h = 0.5f * h * (1.0f + erff(h * 0.70710678118654752f));
        float v = h * w2j;
        #pragma unroll
        for (int o = 16; o; o >>= 1) v += __shfl_xor_sync(0xffffffffu, v, o);
        if (lane == 0) sred[w][g] = v;
    }
    __syncthreads();
    if (j < GT) {
        float st = 0.0f;
        #pragma unroll
        for (int r = 0; r < 8; r++) st += sred[r][j];
        out_stop[g0 + j] = st + b2[0];
    }
}

// ---------------- launch ----------------
extern "C" void kernel_launch(void* const* d_in, const int* in_sizes, int n_in,
                              void* d_out, int out_size) {
    const float* edge_tokens     = (const float*)d_in[0];
    const float* question_tokens = (const float*)d_in[1];
    const int*   edge_batch      = (const int*)d_in[2];
    const int*   selected_mask   = (const int*)d_in[3];
    const float* W_edge          = (const float*)d_in[4];
    const float* W_query         = (const float*)d_in[5];
    const float* att_vec         = (const float*)d_in[6];
    const float* ln_g            = (const float*)d_in[7];
    const float* ln_b            = (const float*)d_in[8];
    const float* W1              = (const float*)d_in[9];
    const float* b1              = (const float*)d_in[10];
    const float* W2              = (const float*)d_in[11];
    const float* b2              = (const float*)d_in[12];

    int E = in_sizes[2];
    float* out      = (float*)d_out;
    float* out_edge = out;             // [E]
    float* out_stop = out + E;         // [G]
    float* out_pool = out + E + G_;    // [G, H]

    k_uv<<<8, 256>>>(W_edge, W_query, att_vec);
    k_qatt<<<G_, 32>>>(question_tokens);
    // main pass: 4 blocks per SM (148*4 = 592), unroll-2
    {
        int blocks = 592, threads = 256;
        int warps = blocks * threads / 32;        // 4736
        int epw = (E + warps - 1) / warps;
        k_main<<<blocks, threads>>>(edge_tokens, edge_batch, selected_mask, E, epw);
    }
    {
        dim3 grid(G_, NSLICE);
        k_comb<<<grid, 256>>>();
    }
    k_fin<<<1, G_>>>();
    {
        int E4 = E / 4;
        if (E4 > 0)
            k_logits<<<(E4 + 255) / 256, 256>>>(edge_batch, out_edge, E4);
        int rem = E - E4 * 4;
        if (rem > 0)
            k_logits_tail<<<(rem + 255) / 256, 256>>>(edge_batch, out_edge, E4 * 4, E);
    }
    k_head<<<G_ / GT, 256>>>(question_tokens, W_edge, ln_g, ln_b, W1, b1, W2, b2,
                             out_stop, out_pool);
}

// round 11
// speedup vs baseline: 1.0484x; 1.0193x over previous
#include <cuda_runtime.h>
#include <math.h>
#include <float.h>

#define H 256
#define G_ 256
#define H2 512
#define E_MAX 524288
#define GT 8                            // graphs per block in k_head
#define LOGEPS -15.942385152878742f     // logf(FLT_EPSILON)

// ---------------- scratch (static device globals; no allocation) ----------------
__device__ float    d_att[E_MAX];      // att score (candidates); -1e38 for selected
__device__ float    d_sumtok[G_ * H];  // segment sum of edge_tokens
__device__ int      d_cnt[G_];         // edges per graph
__device__ float    d_gsum[G_];        // per-graph Σ exp(att) over candidates (absolute domain)
__device__ float    d_off[G_];         // log(gsum)
__device__ float    d_u[H];            // att_vec @ W_edge
__device__ float    d_v[H];            // att_vec @ W_query
__device__ float    d_qatt[G_];        // question_tokens @ v

// ---------------- K1: u = att_vec @ W_edge, v = att_vec @ W_query (8 blocks) ----
__global__ void k_uv(const float* __restrict__ We, const float* __restrict__ Wq,
                     const float* __restrict__ av) {
    __shared__ float sa[H];
    __shared__ float ru[8][32], rv[8][32];
    int tx = threadIdx.x & 31, ty = threadIdx.x >> 5;
    sa[threadIdx.x] = av[threadIdx.x];
    __syncthreads();
    int col = blockIdx.x * 32 + tx;
    float u = 0.0f, v = 0.0f;
    #pragma unroll 4
    for (int j = ty; j < H; j += 8) {
        float a = sa[j];
        u = fmaf(a, We[j * H + col], u);
        v = fmaf(a, Wq[j * H + col], v);
    }
    ru[ty][tx] = u; rv[ty][tx] = v;
    __syncthreads();
    if (ty == 0) {
        float su = 0.0f, sv = 0.0f;
        #pragma unroll
        for (int r = 0; r < 8; r++) { su += ru[r][tx]; sv += rv[r][tx]; }
        d_u[col] = su; d_v[col] = sv;
    }
}

// ---------------- K1b: qatt[g] = question_tokens[g] . v   + scratch init ----------
__global__ void k_qatt(const float* __restrict__ qt) {
    int g = blockIdx.x, lane = threadIdx.x;
    float4 z = make_float4(0.f, 0.f, 0.f, 0.f);
    ((float4*)d_sumtok)[g * 64 + lane]      = z;
    ((float4*)d_sumtok)[g * 64 + 32 + lane] = z;
    if (lane == 0) { d_cnt[g] = 0; d_gsum[g] = 0.0f; }
    const float4* q4 = (const float4*)(qt + g * H);
    const float4* v4 = (const float4*)d_v;
    float4 a = q4[lane], b = q4[lane + 32];
    float4 va = v4[lane], vb = v4[lane + 32];
    float s = a.x*va.x + a.y*va.y + a.z*va.z + a.w*va.w
            + b.x*vb.x + b.y*vb.y + b.z*vb.z + b.w*vb.w;
    #pragma unroll
    for (int o = 16; o; o >>= 1) s += __shfl_xor_sync(0xffffffffu, s, o);
    if (lane == 0) d_qatt[g] = s;
}

// ---------------- K2: main streaming pass (unroll-2, occ-4, absolute expsum) ----
struct RunState {
    int    cur_g;
    float4 cs0, cs1;
    int    cnt;
    float  rsum;       // Σ exp(t) over candidate edges of this run (absolute domain)
};

__device__ __forceinline__ void flush_run(const RunState& st, int lane) {
    float* sp = d_sumtok + st.cur_g * H;
    atomicAdd(sp + 4*lane + 0,       st.cs0.x);
    atomicAdd(sp + 4*lane + 1,       st.cs0.y);
    atomicAdd(sp + 4*lane + 2,       st.cs0.z);
    atomicAdd(sp + 4*lane + 3,       st.cs0.w);
    atomicAdd(sp + 128 + 4*lane + 0, st.cs1.x);
    atomicAdd(sp + 128 + 4*lane + 1, st.cs1.y);
    atomicAdd(sp + 128 + 4*lane + 2, st.cs1.z);
    atomicAdd(sp + 128 + 4*lane + 3, st.cs1.w);
    if (lane == 0) {
        atomicAdd(&d_cnt[st.cur_g], st.cnt);
        atomicAdd(&d_gsum[st.cur_g], st.rsum);
    }
}

__device__ __forceinline__ void reset_run(RunState& st, int g) {
    st.cur_g = g;
    st.cs0 = make_float4(0.f, 0.f, 0.f, 0.f);
    st.cs1 = make_float4(0.f, 0.f, 0.f, 0.f);
    st.cnt = 0; st.rsum = 0.0f;
}

__device__ __forceinline__ void proc_edge(RunState& st, float4 a, float4 b,
                                          float s, int g, int m, int e, int lane) {
    if (g != st.cur_g) {
        flush_run(st, lane);
        reset_run(st, g);
    }
    st.cs0.x += a.x; st.cs0.y += a.y; st.cs0.z += a.z; st.cs0.w += a.w;
    st.cs1.x += b.x; st.cs1.y += b.y; st.cs1.z += b.z; st.cs1.w += b.w;
    float t = s + d_qatt[g];
    t = (t > 0.0f) ? t : 0.2f * t;               // LeakyReLU(0.2)
    if (m == 0) {
        t += 0.5f;                               // frontier bonus (candidates)
        st.rsum += __expf(t);                    // absolute-domain exp (range-safe)
    }
    st.cnt++;
    if (lane == 0) d_att[e] = (m == 0) ? t : -1.0e38f;
}

__device__ __forceinline__ float dot8(float4 a, float4 b, float4 ua, float4 ub) {
    float s = a.x*ua.x; s = fmaf(a.y, ua.y, s); s = fmaf(a.z, ua.z, s);
    s = fmaf(a.w, ua.w, s); s = fmaf(b.x, ub.x, s); s = fmaf(b.y, ub.y, s);
    s = fmaf(b.z, ub.z, s); s = fmaf(b.w, ub.w, s);
    return s;
}

__global__ void __launch_bounds__(256, 4)
k_main(const float* __restrict__ et, const int* __restrict__ batch,
       const int* __restrict__ sel, int E, int epw) {
    int wid  = (blockIdx.x * blockDim.x + threadIdx.x) >> 5;
    int lane = threadIdx.x & 31;
    int start = wid * epw;
    if (start >= E) return;
    int end = min(E, start + epw);

    const float4* u4 = (const float4*)d_u;
    float4 ua = u4[lane], ub = u4[lane + 32];

    RunState st;
    reset_run(st, batch[start]);

    int e = start;
    for (; e + 1 < end; e += 2) {
        const float4* r0 = (const float4*)(et + (size_t)e * H);
        const float4* r1 = (const float4*)(et + (size_t)(e + 1) * H);
        float4 a0 = __ldcs(r0 + lane), b0 = __ldcs(r0 + lane + 32);
        float4 a1 = __ldcs(r1 + lane), b1 = __ldcs(r1 + lane + 32);
        int g0 = batch[e], g1 = batch[e + 1];
        int m0 = sel[e],   m1 = sel[e + 1];

        float s0 = dot8(a0, b0, ua, ub);
        float s1 = dot8(a1, b1, ua, ub);
        #pragma unroll
        for (int o = 16; o; o >>= 1) {
            s0 += __shfl_xor_sync(0xffffffffu, s0, o);
            s1 += __shfl_xor_sync(0xffffffffu, s1, o);
        }
        proc_edge(st, a0, b0, s0, g0, m0, e,     lane);
        proc_edge(st, a1, b1, s1, g1, m1, e + 1, lane);
    }
    if (e < end) {   // tail edge
        const float4* r0 = (const float4*)(et + (size_t)e * H);
        float4 a0 = __ldcs(r0 + lane), b0 = __ldcs(r0 + lane + 32);
        int g0 = batch[e], m0 = sel[e];
        float s0 = dot8(a0, b0, ua, ub);
        #pragma unroll
        for (int o = 16; o; o >>= 1) s0 += __shfl_xor_sync(0xffffffffu, s0, o);
        proc_edge(st, a0, b0, s0, g0, m0, e, lane);
    }
    flush_run(st, lane);
}

// ---------------- K3: finalize d_off = log(gsum) ----------------
__global__ void k_fin() {
    int g = threadIdx.x;
    d_off[g] = logf(fmaxf(d_gsum[g], FLT_EPSILON));
}

// ---------------- K4: edge_logits (vectorized x4) ----------------
__global__ void k_logits(const int* __restrict__ batch, float* __restrict__ out,
                         int E4) {
    int i = blockIdx.x * blockDim.x + threadIdx.x;
    if (i >= E4) return;
    int4   g = ((const int4*)batch)[i];
    float4 a = ((const float4*)d_att)[i];
    float4 r;
    r.x = fmaxf(a.x - d_off[g.x], LOGEPS);
    r.y = fmaxf(a.y - d_off[g.y], LOGEPS);
    r.z = fmaxf(a.z - d_off[g.z], LOGEPS);
    r.w = fmaxf(a.w - d_off[g.w], LOGEPS);
    ((float4*)out)[i] = r;
}
__global__ void k_logits_tail(const int* __restrict__ batch, float* __restrict__ out,
                              int start, int E) {
    int e = start + blockIdx.x * blockDim.x + threadIdx.x;
    if (e >= E) return;
    out[e] = fmaxf(d_att[e] - d_off[batch[e]], LOGEPS);
}

// ---------------- K5: pooled GEMM + stop head (GT graphs per block) ----------------
__global__ void __launch_bounds__(256)
k_head(const float* __restrict__ qt, const float* __restrict__ We,
       const float* __restrict__ lng, const float* __restrict__ lnb,
       const float* __restrict__ W1, const float* __restrict__ b1,
       const float* __restrict__ W2, const float* __restrict__ b2,
       float* __restrict__ out_stop, float* __restrict__ out_pool) {
    __shared__ float spool[GT][H];
    __shared__ float sxn[GT][H2];
    __shared__ float sred[8][GT];
    __shared__ float smu[GT], sinv[GT];
    int g0 = blockIdx.x * GT;
    int j = threadIdx.x;
    int w = j >> 5, lane = j & 31;

    #pragma unroll
    for (int g = 0; g < GT; g++) spool[g][j] = d_sumtok[(g0 + g) * H + j];
    __syncthreads();

    float pj[GT];
    #pragma unroll
    for (int g = 0; g < GT; g++) pj[g] = 0.0f;
    const float4* wr = (const float4*)(We + j * H);
    for (int k = 0; k < H / 4; k++) {
        float4 wv = wr[k];
        #pragma unroll
        for (int g = 0; g < GT; g++) {
            float4 x = ((const float4*)spool[g])[k];
            pj[g] = fmaf(wv.x, x.x, pj[g]); pj[g] = fmaf(wv.y, x.y, pj[g]);
            pj[g] = fmaf(wv.z, x.z, pj[g]); pj[g] = fmaf(wv.w, x.w, pj[g]);
        }
    }
    float x1[GT];
    #pragma unroll
    for (int g = 0; g < GT; g++) {
        float c = (float)max(d_cnt[g0 + g], 1);
        pj[g] /= c;
        out_pool[(g0 + g) * H + j] = pj[g];
        x1[g] = qt[(g0 + g) * H + j];
    }

    #pragma unroll
    for (int g = 0; g < GT; g++) {
        float v = pj[g] + x1[g];
        #pragma unroll
        for (int o = 16; o; o >>= 1) v += __shfl_xor_sync(0xffffffffu, v, o);
        if (lane == 0) sred[w][g] = v;
    }
    __syncthreads();
    if (j < GT) {
        float tot = 0.0f;
        #pragma unroll
        for (int r = 0; r < 8; r++) tot += sred[r][j];
        smu[j] = tot * (1.0f / 512.0f);
    }
    __syncthreads();
    #pragma unroll
    for (int g = 0; g < GT; g++) {
        float d0 = pj[g] - smu[g], d1 = x1[g] - smu[g];
        float v = d0 * d0 + d1 * d1;
        #pragma unroll
        for (int o = 16; o; o >>= 1) v += __shfl_xor_sync(0xffffffffu, v, o);
        if (lane == 0) sred[w][g] = v;
    }
    __syncthreads();
    if (j < GT) {
        float var = 0.0f;
        #pragma unroll
        for (int r = 0; r < 8; r++) var += sred[r][j];
        sinv[j] = rsqrtf(var * (1.0f / 512.0f) + 1e-5f);
    }
    __syncthreads();
    float g0v = lng[j], g1v = lng[H + j], b0v = lnb[j], b1v = lnb[H + j];
    #pragma unroll
    for (int g = 0; g < GT; g++) {
        sxn[g][j]     = (pj[g] - smu[g]) * sinv[g] * g0v + b0v;
        sxn[g][H + j] = (x1[g] - smu[g]) * sinv[g] * g1v + b1v;
    }
    __syncthreads();

    float hh[GT];
    float bb = b1[j];
    #pragma unroll
    for (int g = 0; g < GT; g++) hh[g] = bb;
    const float4* w1r = (const float4*)(W1 + j * H2);
    for (int k = 0; k < H2 / 4; k++) {
        float4 wv = w1r[k];
        #pragma unroll
        for (int g = 0; g < GT; g++) {
            float4 x = ((const float4*)sxn[g])[k];
            hh[g] = fmaf(wv.x, x.x, hh[g]); hh[g] = fmaf(wv.y, x.y, hh[g]);
            hh[g] = fmaf(wv.z, x.z, hh[g]); hh[g] = fmaf(wv.w, x.w, hh[g]);
        }
    }
    float w2j = W2[j];
    #pragma unroll
    for (int g = 0; g < GT; g++) {
        float h = hh[g];
        h = 0.5f * h * (1.0f + erff(h * 0.70710678118654752f));
        float v = h * w2j;
        #pragma unroll
        for (int o = 16; o; o >>= 1) v += __shfl_xor_sync(0xffffffffu, v, o);
        if (lane == 0) sred[w][g] = v;
    }
    __syncthreads();
    if (j < GT) {
        float st = 0.0f;
        #pragma unroll
        for (int r = 0; r < 8; r++) st += sred[r][j];
        out_stop[g0 + j] = st + b2[0];
    }
}

// ---------------- launch ----------------
extern "C" void kernel_launch(void* const* d_in, const int* in_sizes, int n_in,
                              void* d_out, int out_size) {
    const float* edge_tokens     = (const float*)d_in[0];
    const float* question_tokens = (const float*)d_in[1];
    const int*   edge_batch      = (const int*)d_in[2];
    const int*   selected_mask   = (const int*)d_in[3];
    const float* W_edge          = (const float*)d_in[4];
    const float* W_query         = (const float*)d_in[5];
    const float* att_vec         = (const float*)d_in[6];
    const float* ln_g            = (const float*)d_in[7];
    const float* ln_b            = (const float*)d_in[8];
    const float* W1              = (const float*)d_in[9];
    const float* b1              = (const float*)d_in[10];
    const float* W2              = (const float*)d_in[11];
    const float* b2              = (const float*)d_in[12];

    int E = in_sizes[2];
    float* out      = (float*)d_out;
    float* out_edge = out;             // [E]
    float* out_stop = out + E;         // [G]
    float* out_pool = out + E + G_;    // [G, H]

    k_uv<<<8, 256>>>(W_edge, W_query, att_vec);
    k_qatt<<<G_, 32>>>(question_tokens);
    // main pass: 4 blocks per SM (148*4 = 592), unroll-2
    {
        int blocks = 592, threads = 256;
        int warps = blocks * threads / 32;        // 4736
        int epw = (E + warps - 1) / warps;
        k_main<<<blocks, threads>>>(edge_tokens, edge_batch, selected_mask, E, epw);
    }
    k_fin<<<1, G_>>>();
    {
        int E4 = E / 4;
        if (E4 > 0)
            k_logits<<<(E4 + 255) / 256, 256>>>(edge_batch, out_edge, E4);
        int rem = E - E4 * 4;
        if (rem > 0)
            k_logits_tail<<<(rem + 255) / 256, 256>>>(edge_batch, out_edge, E4 * 4, E);
    }
    k_head<<<G_ / GT, 256>>>(question_tokens, W_edge, ln_g, ln_b, W1, b1, W2, b2,
                             out_stop, out_pool);
}

// round 12
// speedup vs baseline: 1.0978x; 1.0472x over previous
#include <cuda_runtime.h>
#include <math.h>
#include <float.h>

#define H 256
#define G_ 256
#define H2 512
#define E_MAX 524288
#define GT 8                            // graphs per block in head role
#define NHEADB (G_ / GT)                // 32 head blocks
#define LOGEPS -15.942385152878742f     // logf(FLT_EPSILON)

// ---------------- scratch (static device globals; no allocation) ----------------
__device__ float    d_att[E_MAX];      // att score (candidates); -1e38 for selected
__device__ float    d_sumtok[G_ * H];  // segment sum of edge_tokens
__device__ int      d_cnt[G_];         // edges per graph
__device__ float    d_gsum[G_];        // per-graph Σ exp(att) over candidates
__device__ float    d_u[H];            // att_vec @ W_edge
__device__ float    d_v[H];            // att_vec @ W_query
__device__ float    d_qatt[G_];        // question_tokens @ v

// ---------------- K1: u = att_vec @ W_edge, v = att_vec @ W_query (8 blocks) ----
__global__ void k_uv(const float* __restrict__ We, const float* __restrict__ Wq,
                     const float* __restrict__ av) {
    __shared__ float sa[H];
    __shared__ float ru[8][32], rv[8][32];
    int tx = threadIdx.x & 31, ty = threadIdx.x >> 5;
    sa[threadIdx.x] = av[threadIdx.x];
    __syncthreads();
    int col = blockIdx.x * 32 + tx;
    float u = 0.0f, v = 0.0f;
    #pragma unroll 4
    for (int j = ty; j < H; j += 8) {
        float a = sa[j];
        u = fmaf(a, We[j * H + col], u);
        v = fmaf(a, Wq[j * H + col], v);
    }
    ru[ty][tx] = u; rv[ty][tx] = v;
    __syncthreads();
    if (ty == 0) {
        float su = 0.0f, sv = 0.0f;
        #pragma unroll
        for (int r = 0; r < 8; r++) { su += ru[r][tx]; sv += rv[r][tx]; }
        d_u[col] = su; d_v[col] = sv;
    }
}

// ---------------- K1b: qatt[g] = question_tokens[g] . v   + scratch init ----------
__global__ void k_qatt(const float* __restrict__ qt) {
    int g = blockIdx.x, lane = threadIdx.x;
    float4 z = make_float4(0.f, 0.f, 0.f, 0.f);
    ((float4*)d_sumtok)[g * 64 + lane]      = z;
    ((float4*)d_sumtok)[g * 64 + 32 + lane] = z;
    if (lane == 0) { d_cnt[g] = 0; d_gsum[g] = 0.0f; }
    const float4* q4 = (const float4*)(qt + g * H);
    const float4* v4 = (const float4*)d_v;
    float4 a = q4[lane], b = q4[lane + 32];
    float4 va = v4[lane], vb = v4[lane + 32];
    float s = a.x*va.x + a.y*va.y + a.z*va.z + a.w*va.w
            + b.x*vb.x + b.y*vb.y + b.z*vb.z + b.w*vb.w;
    #pragma unroll
    for (int o = 16; o; o >>= 1) s += __shfl_xor_sync(0xffffffffu, s, o);
    if (lane == 0) d_qatt[g] = s;
}

// ---------------- K2: main streaming pass (unroll-2, occ-4, absolute expsum) ----
struct RunState {
    int    cur_g;
    float4 cs0, cs1;
    int    cnt;
    float  rsum;
};

__device__ __forceinline__ void flush_run(const RunState& st, int lane) {
    float* sp = d_sumtok + st.cur_g * H;
    atomicAdd(sp + 4*lane + 0,       st.cs0.x);
    atomicAdd(sp + 4*lane + 1,       st.cs0.y);
    atomicAdd(sp + 4*lane + 2,       st.cs0.z);
    atomicAdd(sp + 4*lane + 3,       st.cs0.w);
    atomicAdd(sp + 128 + 4*lane + 0, st.cs1.x);
    atomicAdd(sp + 128 + 4*lane + 1, st.cs1.y);
    atomicAdd(sp + 128 + 4*lane + 2, st.cs1.z);
    atomicAdd(sp + 128 + 4*lane + 3, st.cs1.w);
    if (lane == 0) {
        atomicAdd(&d_cnt[st.cur_g], st.cnt);
        atomicAdd(&d_gsum[st.cur_g], st.rsum);
    }
}

__device__ __forceinline__ void reset_run(RunState& st, int g) {
    st.cur_g = g;
    st.cs0 = make_float4(0.f, 0.f, 0.f, 0.f);
    st.cs1 = make_float4(0.f, 0.f, 0.f, 0.f);
    st.cnt = 0; st.rsum = 0.0f;
}

__device__ __forceinline__ void proc_edge(RunState& st, float4 a, float4 b,
                                          float s, int g, int m, int e, int lane) {
    if (g != st.cur_g) {
        flush_run(st, lane);
        reset_run(st, g);
    }
    st.cs0.x += a.x; st.cs0.y += a.y; st.cs0.z += a.z; st.cs0.w += a.w;
    st.cs1.x += b.x; st.cs1.y += b.y; st.cs1.z += b.z; st.cs1.w += b.w;
    float t = s + d_qatt[g];
    t = (t > 0.0f) ? t : 0.2f * t;               // LeakyReLU(0.2)
    if (m == 0) {
        t += 0.5f;                               // frontier bonus (candidates)
        st.rsum += __expf(t);                    // absolute-domain exp (range-safe)
    }
    st.cnt++;
    if (lane == 0) d_att[e] = (m == 0) ? t : -1.0e38f;
}

__device__ __forceinline__ float dot8(float4 a, float4 b, float4 ua, float4 ub) {
    float s = a.x*ua.x; s = fmaf(a.y, ua.y, s); s = fmaf(a.z, ua.z, s);
    s = fmaf(a.w, ua.w, s); s = fmaf(b.x, ub.x, s); s = fmaf(b.y, ub.y, s);
    s = fmaf(b.z, ub.z, s); s = fmaf(b.w, ub.w, s);
    return s;
}

__global__ void __launch_bounds__(256, 4)
k_main(const float* __restrict__ et, const int* __restrict__ batch,
       const int* __restrict__ sel, int E, int epw) {
    int wid  = (blockIdx.x * blockDim.x + threadIdx.x) >> 5;
    int lane = threadIdx.x & 31;
    int start = wid * epw;
    if (start >= E) return;
    int end = min(E, start + epw);

    const float4* u4 = (const float4*)d_u;
    float4 ua = u4[lane], ub = u4[lane + 32];

    RunState st;
    reset_run(st, batch[start]);

    int e = start;
    for (; e + 1 < end; e += 2) {
        const float4* r0 = (const float4*)(et + (size_t)e * H);
        const float4* r1 = (const float4*)(et + (size_t)(e + 1) * H);
        float4 a0 = __ldcs(r0 + lane), b0 = __ldcs(r0 + lane + 32);
        float4 a1 = __ldcs(r1 + lane), b1 = __ldcs(r1 + lane + 32);
        int g0 = batch[e], g1 = batch[e + 1];
        int m0 = sel[e],   m1 = sel[e + 1];

        float s0 = dot8(a0, b0, ua, ub);
        float s1 = dot8(a1, b1, ua, ub);
        #pragma unroll
        for (int o = 16; o; o >>= 1) {
            s0 += __shfl_xor_sync(0xffffffffu, s0, o);
            s1 += __shfl_xor_sync(0xffffffffu, s1, o);
        }
        proc_edge(st, a0, b0, s0, g0, m0, e,     lane);
        proc_edge(st, a1, b1, s1, g1, m1, e + 1, lane);
    }
    if (e < end) {   // tail edge
        const float4* r0 = (const float4*)(et + (size_t)e * H);
        float4 a0 = __ldcs(r0 + lane), b0 = __ldcs(r0 + lane + 32);
        int g0 = batch[e], m0 = sel[e];
        float s0 = dot8(a0, b0, ua, ub);
        #pragma unroll
        for (int o = 16; o; o >>= 1) s0 += __shfl_xor_sync(0xffffffffu, s0, o);
        proc_edge(st, a0, b0, s0, g0, m0, e, lane);
    }
    flush_run(st, lane);
}

// ---------------- K3 (fused): head blocks (0..31) + logits blocks (32..) --------
__device__ __forceinline__ void do_head(const float* __restrict__ qt,
                                        const float* __restrict__ We,
                                        const float* __restrict__ lng,
                                        const float* __restrict__ lnb,
                                        const float* __restrict__ W1,
                                        const float* __restrict__ b1,
                                        const float* __restrict__ W2,
                                        const float* __restrict__ b2,
                                        float* __restrict__ out_stop,
                                        float* __restrict__ out_pool,
                                        int g0) {
    __shared__ float spool[GT][H];
    __shared__ float sxn[GT][H2];
    __shared__ float sred[8][GT];
    __shared__ float smu[GT], sinv[GT];
    int j = threadIdx.x;
    int w = j >> 5, lane = j & 31;

    #pragma unroll
    for (int g = 0; g < GT; g++) spool[g][j] = d_sumtok[(g0 + g) * H + j];
    __syncthreads();

    float pj[GT];
    #pragma unroll
    for (int g = 0; g < GT; g++) pj[g] = 0.0f;
    const float4* wr = (const float4*)(We + j * H);
    for (int k = 0; k < H / 4; k++) {
        float4 wv = wr[k];
        #pragma unroll
        for (int g = 0; g < GT; g++) {
            float4 x = ((const float4*)spool[g])[k];
            pj[g] = fmaf(wv.x, x.x, pj[g]); pj[g] = fmaf(wv.y, x.y, pj[g]);
            pj[g] = fmaf(wv.z, x.z, pj[g]); pj[g] = fmaf(wv.w, x.w, pj[g]);
        }
    }
    float x1[GT];
    #pragma unroll
    for (int g = 0; g < GT; g++) {
        float c = (float)max(d_cnt[g0 + g], 1);
        pj[g] /= c;
        out_pool[(g0 + g) * H + j] = pj[g];
        x1[g] = qt[(g0 + g) * H + j];
    }

    #pragma unroll
    for (int g = 0; g < GT; g++) {
        float v = pj[g] + x1[g];
        #pragma unroll
        for (int o = 16; o; o >>= 1) v += __shfl_xor_sync(0xffffffffu, v, o);
        if (lane == 0) sred[w][g] = v;
    }
    __syncthreads();
    if (j < GT) {
        float tot = 0.0f;
        #pragma unroll
        for (int r = 0; r < 8; r++) tot += sred[r][j];
        smu[j] = tot * (1.0f / 512.0f);
    }
    __syncthreads();
    #pragma unroll
    for (int g = 0; g < GT; g++) {
        float d0 = pj[g] - smu[g], d1 = x1[g] - smu[g];
        float v = d0 * d0 + d1 * d1;
        #pragma unroll
        for (int o = 16; o; o >>= 1) v += __shfl_xor_sync(0xffffffffu, v, o);
        if (lane == 0) sred[w][g] = v;
    }
    __syncthreads();
    if (j < GT) {
        float var = 0.0f;
        #pragma unroll
        for (int r = 0; r < 8; r++) var += sred[r][j];
        sinv[j] = rsqrtf(var * (1.0f / 512.0f) + 1e-5f);
    }
    __syncthreads();
    float g0v = lng[j], g1v = lng[H + j], b0v = lnb[j], b1v = lnb[H + j];
    #pragma unroll
    for (int g = 0; g < GT; g++) {
        sxn[g][j]     = (pj[g] - smu[g]) * sinv[g] * g0v + b0v;
        sxn[g][H + j] = (x1[g] - smu[g]) * sinv[g] * g1v + b1v;
    }
    __syncthreads();

    float hh[GT];
    float bb = b1[j];
    #pragma unroll
    for (int g = 0; g < GT; g++) hh[g] = bb;
    const float4* w1r = (const float4*)(W1 + j * H2);
    for (int k = 0; k < H2 / 4; k++) {
        float4 wv = w1r[k];
        #pragma unroll
        for (int g = 0; g < GT; g++) {
            float4 x = ((const float4*)sxn[g])[k];
            hh[g] = fmaf(wv.x, x.x, hh[g]); hh[g] = fmaf(wv.y, x.y, hh[g]);
            hh[g] = fmaf(wv.z, x.z, hh[g]); hh[g] = fmaf(wv.w, x.w, hh[g]);
        }
    }
    float w2j = W2[j];
    #pragma unroll
    for (int g = 0; g < GT; g++) {
        float h = hh[g];
        h = 0.5f * h * (1.0f + erff(h * 0.70710678118654752f));
        float v = h * w2j;
        #pragma unroll
        for (int o = 16; o; o >>= 1) v += __shfl_xor_sync(0xffffffffu, v, o);
        if (lane == 0) sred[w][g] = v;
    }
    __syncthreads();
    if (j < GT) {
        float st = 0.0f;
        #pragma unroll
        for (int r = 0; r < 8; r++) st += sred[r][j];
        out_stop[g0 + j] = st + b2[0];
    }
}

__global__ void __launch_bounds__(256)
k_post(const int* __restrict__ batch,
       const float* __restrict__ qt, const float* __restrict__ We,
       const float* __restrict__ lng, const float* __restrict__ lnb,
       const float* __restrict__ W1, const float* __restrict__ b1,
       const float* __restrict__ W2, const float* __restrict__ b2,
       float* __restrict__ out_edge, float* __restrict__ out_stop,
       float* __restrict__ out_pool, int E4) {
    if (blockIdx.x < NHEADB) {
        do_head(qt, We, lng, lnb, W1, b1, W2, b2, out_stop, out_pool,
                blockIdx.x * GT);
        return;
    }
    // logits role
    int i = (blockIdx.x - NHEADB) * blockDim.x + threadIdx.x;
    if (i >= E4) return;
    int4   g = ((const int4*)batch)[i];
    float4 a = ((const float4*)d_att)[i];
    float4 r;
    r.x = fmaxf(a.x - __logf(fmaxf(d_gsum[g.x], FLT_EPSILON)), LOGEPS);
    r.y = fmaxf(a.y - __logf(fmaxf(d_gsum[g.y], FLT_EPSILON)), LOGEPS);
    r.z = fmaxf(a.z - __logf(fmaxf(d_gsum[g.z], FLT_EPSILON)), LOGEPS);
    r.w = fmaxf(a.w - __logf(fmaxf(d_gsum[g.w], FLT_EPSILON)), LOGEPS);
    ((float4*)out_edge)[i] = r;
}

// tail edges (only if E % 4 != 0)
__global__ void k_logits_tail(const int* __restrict__ batch, float* __restrict__ out,
                              int start, int E) {
    int e = start + blockIdx.x * blockDim.x + threadIdx.x;
    if (e >= E) return;
    out[e] = fmaxf(d_att[e] - __logf(fmaxf(d_gsum[batch[e]], FLT_EPSILON)), LOGEPS);
}

// ---------------- launch ----------------
extern "C" void kernel_launch(void* const* d_in, const int* in_sizes, int n_in,
                              void* d_out, int out_size) {
    const float* edge_tokens     = (const float*)d_in[0];
    const float* question_tokens = (const float*)d_in[1];
    const int*   edge_batch      = (const int*)d_in[2];
    const int*   selected_mask   = (const int*)d_in[3];
    const float* W_edge          = (const float*)d_in[4];
    const float* W_query         = (const float*)d_in[5];
    const float* att_vec         = (const float*)d_in[6];
    const float* ln_g            = (const float*)d_in[7];
    const float* ln_b            = (const float*)d_in[8];
    const float* W1              = (const float*)d_in[9];
    const float* b1              = (const float*)d_in[10];
    const float* W2              = (const float*)d_in[11];
    const float* b2              = (const float*)d_in[12];

    int E = in_sizes[2];
    float* out      = (float*)d_out;
    float* out_edge = out;             // [E]
    float* out_stop = out + E;         // [G]
    float* out_pool = out + E + G_;    // [G, H]

    k_uv<<<8, 256>>>(W_edge, W_query, att_vec);
    k_qatt<<<G_, 32>>>(question_tokens);
    // main pass: 4 blocks per SM (148*4 = 592), unroll-2
    {
        int blocks = 592, threads = 256;
        int warps = blocks * threads / 32;        // 4736
        int epw = (E + warps - 1) / warps;
        k_main<<<blocks, threads>>>(edge_tokens, edge_batch, selected_mask, E, epw);
    }
    // fused logits + head
    {
        int E4 = E / 4;
        int nblocks = NHEADB + (E4 + 255) / 256;
        k_post<<<nblocks, 256>>>(edge_batch, question_tokens, W_edge,
                                 ln_g, ln_b, W1, b1, W2, b2,
                                 out_edge, out_stop, out_pool, E4);
        int rem = E - E4 * 4;
        if (rem > 0)
            k_logits_tail<<<(rem + 255) / 256, 256>>>(edge_batch, out_edge, E4 * 4, E);
    }
}

// round 13
// speedup vs baseline: 1.3129x; 1.1959x over previous
#include <cuda_runtime.h>
#include <math.h>
#include <float.h>

#define H 256
#define G_ 256
#define H2 512
#define E_MAX 524288
#define GT 4                            // graphs per head block
#define NHEADB (G_ / GT)                // 64 head blocks
#define LOGEPS -15.942385152878742f     // logf(FLT_EPSILON)

// ---------------- scratch (static device globals; no allocation) ----------------
__device__ float    d_att[E_MAX];      // att score (candidates); -1e38 for selected
__device__ float    d_sumtok[G_ * H];  // segment sum of edge_tokens
__device__ int      d_cnt[G_];         // edges per graph
__device__ float    d_gsum[G_];        // per-graph Σ exp(att) over candidates
__device__ float    d_u[H];            // att_vec @ W_edge
__device__ float    d_v[H];            // att_vec @ W_query
__device__ float    d_qatt[G_];        // question_tokens @ v

// ---------------- K1: u = att_vec @ W_edge, v = att_vec @ W_query (8 blocks) ----
__global__ void k_uv(const float* __restrict__ We, const float* __restrict__ Wq,
                     const float* __restrict__ av) {
    __shared__ float sa[H];
    __shared__ float ru[8][32], rv[8][32];
    int tx = threadIdx.x & 31, ty = threadIdx.x >> 5;
    sa[threadIdx.x] = av[threadIdx.x];
    __syncthreads();
    int col = blockIdx.x * 32 + tx;
    float u = 0.0f, v = 0.0f;
    #pragma unroll 4
    for (int j = ty; j < H; j += 8) {
        float a = sa[j];
        u = fmaf(a, We[j * H + col], u);
        v = fmaf(a, Wq[j * H + col], v);
    }
    ru[ty][tx] = u; rv[ty][tx] = v;
    __syncthreads();
    if (ty == 0) {
        float su = 0.0f, sv = 0.0f;
        #pragma unroll
        for (int r = 0; r < 8; r++) { su += ru[r][tx]; sv += rv[r][tx]; }
        d_u[col] = su; d_v[col] = sv;
    }
}

// ---------------- K1b: qatt[g] = question_tokens[g] . v   + scratch init ----------
__global__ void k_qatt(const float* __restrict__ qt) {
    int g = blockIdx.x, lane = threadIdx.x;
    float4 z = make_float4(0.f, 0.f, 0.f, 0.f);
    ((float4*)d_sumtok)[g * 64 + lane]      = z;
    ((float4*)d_sumtok)[g * 64 + 32 + lane] = z;
    if (lane == 0) { d_cnt[g] = 0; d_gsum[g] = 0.0f; }
    const float4* q4 = (const float4*)(qt + g * H);
    const float4* v4 = (const float4*)d_v;
    float4 a = q4[lane], b = q4[lane + 32];
    float4 va = v4[lane], vb = v4[lane + 32];
    float s = a.x*va.x + a.y*va.y + a.z*va.z + a.w*va.w
            + b.x*vb.x + b.y*vb.y + b.z*vb.z + b.w*vb.w;
    #pragma unroll
    for (int o = 16; o; o >>= 1) s += __shfl_xor_sync(0xffffffffu, s, o);
    if (lane == 0) d_qatt[g] = s;
}

// ---------------- K2: main streaming pass (unroll-2, occ-4, absolute expsum) ----
struct RunState {
    int    cur_g;
    float4 cs0, cs1;
    int    cnt;
    float  rsum;
};

__device__ __forceinline__ void flush_run(const RunState& st, int lane) {
    float* sp = d_sumtok + st.cur_g * H;
    atomicAdd(sp + 4*lane + 0,       st.cs0.x);
    atomicAdd(sp + 4*lane + 1,       st.cs0.y);
    atomicAdd(sp + 4*lane + 2,       st.cs0.z);
    atomicAdd(sp + 4*lane + 3,       st.cs0.w);
    atomicAdd(sp + 128 + 4*lane + 0, st.cs1.x);
    atomicAdd(sp + 128 + 4*lane + 1, st.cs1.y);
    atomicAdd(sp + 128 + 4*lane + 2, st.cs1.z);
    atomicAdd(sp + 128 + 4*lane + 3, st.cs1.w);
    if (lane == 0) {
        atomicAdd(&d_cnt[st.cur_g], st.cnt);
        atomicAdd(&d_gsum[st.cur_g], st.rsum);
    }
}

__device__ __forceinline__ void reset_run(RunState& st, int g) {
    st.cur_g = g;
    st.cs0 = make_float4(0.f, 0.f, 0.f, 0.f);
    st.cs1 = make_float4(0.f, 0.f, 0.f, 0.f);
    st.cnt = 0; st.rsum = 0.0f;
}

__device__ __forceinline__ void proc_edge(RunState& st, float4 a, float4 b,
                                          float s, int g, int m, int e, int lane) {
    if (g != st.cur_g) {
        flush_run(st, lane);
        reset_run(st, g);
    }
    st.cs0.x += a.x; st.cs0.y += a.y; st.cs0.z += a.z; st.cs0.w += a.w;
    st.cs1.x += b.x; st.cs1.y += b.y; st.cs1.z += b.z; st.cs1.w += b.w;
    float t = s + d_qatt[g];
    t = (t > 0.0f) ? t : 0.2f * t;               // LeakyReLU(0.2)
    if (m == 0) {
        t += 0.5f;                               // frontier bonus (candidates)
        st.rsum += __expf(t);                    // absolute-domain exp (range-safe)
    }
    st.cnt++;
    if (lane == 0) d_att[e] = (m == 0) ? t : -1.0e38f;
}

__device__ __forceinline__ float dot8(float4 a, float4 b, float4 ua, float4 ub) {
    float s = a.x*ua.x; s = fmaf(a.y, ua.y, s); s = fmaf(a.z, ua.z, s);
    s = fmaf(a.w, ua.w, s); s = fmaf(b.x, ub.x, s); s = fmaf(b.y, ub.y, s);
    s = fmaf(b.z, ub.z, s); s = fmaf(b.w, ub.w, s);
    return s;
}

__global__ void __launch_bounds__(256, 4)
k_main(const float* __restrict__ et, const int* __restrict__ batch,
       const int* __restrict__ sel, int E, int epw) {
    int wid  = (blockIdx.x * blockDim.x + threadIdx.x) >> 5;
    int lane = threadIdx.x & 31;
    int start = wid * epw;
    if (start >= E) return;
    int end = min(E, start + epw);

    const float4* u4 = (const float4*)d_u;
    float4 ua = u4[lane], ub = u4[lane + 32];

    RunState st;
    reset_run(st, batch[start]);

    int e = start;
    for (; e + 1 < end; e += 2) {
        const float4* r0 = (const float4*)(et + (size_t)e * H);
        const float4* r1 = (const float4*)(et + (size_t)(e + 1) * H);
        float4 a0 = __ldcs(r0 + lane), b0 = __ldcs(r0 + lane + 32);
        float4 a1 = __ldcs(r1 + lane), b1 = __ldcs(r1 + lane + 32);
        int g0 = batch[e], g1 = batch[e + 1];
        int m0 = sel[e],   m1 = sel[e + 1];

        float s0 = dot8(a0, b0, ua, ub);
        float s1 = dot8(a1, b1, ua, ub);
        #pragma unroll
        for (int o = 16; o; o >>= 1) {
            s0 += __shfl_xor_sync(0xffffffffu, s0, o);
            s1 += __shfl_xor_sync(0xffffffffu, s1, o);
        }
        proc_edge(st, a0, b0, s0, g0, m0, e,     lane);
        proc_edge(st, a1, b1, s1, g1, m1, e + 1, lane);
    }
    if (e < end) {   // tail edge
        const float4* r0 = (const float4*)(et + (size_t)e * H);
        float4 a0 = __ldcs(r0 + lane), b0 = __ldcs(r0 + lane + 32);
        int g0 = batch[e], m0 = sel[e];
        float s0 = dot8(a0, b0, ua, ub);
        #pragma unroll
        for (int o = 16; o; o >>= 1) s0 += __shfl_xor_sync(0xffffffffu, s0, o);
        proc_edge(st, a0, b0, s0, g0, m0, e, lane);
    }
    flush_run(st, lane);
}

// ---------------- K3 (fused): head blocks (0..63, warp-per-row) + logits --------
__device__ __forceinline__ void do_head(const float* __restrict__ qt,
                                        const float* __restrict__ We,
                                        const float* __restrict__ lng,
                                        const float* __restrict__ lnb,
                                        const float* __restrict__ W1,
                                        const float* __restrict__ b1,
                                        const float* __restrict__ W2,
                                        const float* __restrict__ b2,
                                        float* __restrict__ out_stop,
                                        float* __restrict__ out_pool,
                                        int g0) {
    __shared__ float spool[GT][H];     // 4 KB: segment sums
    __shared__ float ppool[GT][H];     // 4 KB: pooled
    __shared__ float sxn[GT][H2];      // 8 KB: layernormed input
    __shared__ float sh1[GT][H];       // 4 KB: pre-GELU hidden
    __shared__ float sred[8][GT];
    __shared__ float smu[GT], sinv[GT];
    int j = threadIdx.x;
    int w = j >> 5, lane = j & 31;

    #pragma unroll
    for (int g = 0; g < GT; g++) spool[g][j] = d_sumtok[(g0 + g) * H + j];
    __syncthreads();

    float cinv[GT];
    #pragma unroll
    for (int g = 0; g < GT; g++) cinv[g] = 1.0f / (float)max(d_cnt[g0 + g], 1);

    // ---- Phase A: pooled = (We @ spool) / cnt, warp-per-row (coalesced) ----
    #pragma unroll 2
    for (int r = 0; r < 32; r++) {
        int row = w * 32 + r;
        const float4* wr = (const float4*)(We + row * H);
        float4 a = wr[lane], b = wr[lane + 32];          // coalesced 128B loads
        float s[GT];
        #pragma unroll
        for (int g = 0; g < GT; g++) {
            float4 xa = ((const float4*)spool[g])[lane];
            float4 xb = ((const float4*)spool[g])[lane + 32];
            s[g] = dot8(a, b, xa, xb);
        }
        #pragma unroll
        for (int o = 16; o; o >>= 1) {
            #pragma unroll
            for (int g = 0; g < GT; g++)
                s[g] += __shfl_xor_sync(0xffffffffu, s[g], o);
        }
        if (lane == 0) {
            #pragma unroll
            for (int g = 0; g < GT; g++) ppool[g][row] = s[g] * cinv[g];
        }
    }
    __syncthreads();

    // write pooled output (coalesced), gather per-column values
    float pj[GT], x1[GT];
    #pragma unroll
    for (int g = 0; g < GT; g++) {
        pj[g] = ppool[g][j];
        out_pool[(g0 + g) * H + j] = pj[g];
        x1[g] = qt[(g0 + g) * H + j];
    }

    // ---- Phase B: LayerNorm over 512 ----
    #pragma unroll
    for (int g = 0; g < GT; g++) {
        float v = pj[g] + x1[g];
        #pragma unroll
        for (int o = 16; o; o >>= 1) v += __shfl_xor_sync(0xffffffffu, v, o);
        if (lane == 0) sred[w][g] = v;
    }
    __syncthreads();
    if (j < GT) {
        float tot = 0.0f;
        #pragma unroll
        for (int r = 0; r < 8; r++) tot += sred[r][j];
        smu[j] = tot * (1.0f / 512.0f);
    }
    __syncthreads();
    #pragma unroll
    for (int g = 0; g < GT; g++) {
        float d0 = pj[g] - smu[g], d1 = x1[g] - smu[g];
        float v = d0 * d0 + d1 * d1;
        #pragma unroll
        for (int o = 16; o; o >>= 1) v += __shfl_xor_sync(0xffffffffu, v, o);
        if (lane == 0) sred[w][g] = v;
    }
    __syncthreads();
    if (j < GT) {
        float var = 0.0f;
        #pragma unroll
        for (int r = 0; r < 8; r++) var += sred[r][j];
        sinv[j] = rsqrtf(var * (1.0f / 512.0f) + 1e-5f);
    }
    __syncthreads();
    float g0v = lng[j], g1v = lng[H + j], b0v = lnb[j], b1v = lnb[H + j];
    #pragma unroll
    for (int g = 0; g < GT; g++) {
        sxn[g][j]     = (pj[g] - smu[g]) * sinv[g] * g0v + b0v;
        sxn[g][H + j] = (x1[g] - smu[g]) * sinv[g] * g1v + b1v;
    }
    __syncthreads();

    // ---- Phase C: h1pre = W1 @ sxn, warp-per-row (coalesced) ----
    #pragma unroll 2
    for (int r = 0; r < 32; r++) {
        int row = w * 32 + r;
        const float4* w1r = (const float4*)(W1 + row * H2);
        float4 a = w1r[lane], b = w1r[lane + 32];
        float4 c = w1r[lane + 64], d = w1r[lane + 96];   // 4 coalesced loads
        float s[GT];
        #pragma unroll
        for (int g = 0; g < GT; g++) {
            const float4* x = (const float4*)sxn[g];
            s[g] = dot8(a, b, x[lane], x[lane + 32])
                 + dot8(c, d, x[lane + 64], x[lane + 96]);
        }
        #pragma unroll
        for (int o = 16; o; o >>= 1) {
            #pragma unroll
            for (int g = 0; g < GT; g++)
                s[g] += __shfl_xor_sync(0xffffffffu, s[g], o);
        }
        if (lane == 0) {
            #pragma unroll
            for (int g = 0; g < GT; g++) sh1[g][row] = s[g];
        }
    }
    __syncthreads();

    // ---- Phase D: GELU + W2 reduce (thread-per-column) ----
    float bb = b1[j], w2j = W2[j];
    #pragma unroll
    for (int g = 0; g < GT; g++) {
        float h = sh1[g][j] + bb;
        h = 0.5f * h * (1.0f + erff(h * 0.70710678118654752f));
        float v = h * w2j;
        #pragma unroll
        for (int o = 16; o; o >>= 1) v += __shfl_xor_sync(0xffffffffu, v, o);
        if (lane == 0) sred[w][g] = v;
    }
    __syncthreads();
    if (j < GT) {
        float st = 0.0f;
        #pragma unroll
        for (int r = 0; r < 8; r++) st += sred[r][j];
        out_stop[g0 + j] = st + b2[0];
    }
}

__global__ void __launch_bounds__(256)
k_post(const int* __restrict__ batch,
       const float* __restrict__ qt, const float* __restrict__ We,
       const float* __restrict__ lng, const float* __restrict__ lnb,
       const float* __restrict__ W1, const float* __restrict__ b1,
       const float* __restrict__ W2, const float* __restrict__ b2,
       float* __restrict__ out_edge, float* __restrict__ out_stop,
       float* __restrict__ out_pool, int E4) {
    if (blockIdx.x < NHEADB) {
        do_head(qt, We, lng, lnb, W1, b1, W2, b2, out_stop, out_pool,
                blockIdx.x * GT);
        return;
    }
    // logits role: 2 vec4 items per thread (8 edges)
    int base = (blockIdx.x - NHEADB) * 512 + threadIdx.x;
    #pragma unroll
    for (int rep = 0; rep < 2; rep++) {
        int i = base + rep * 256;
        if (i < E4) {
            int4   g = ((const int4*)batch)[i];
            float4 a = ((const float4*)d_att)[i];
            float4 r;
            r.x = fmaxf(a.x - __logf(fmaxf(d_gsum[g.x], FLT_EPSILON)), LOGEPS);
            r.y = fmaxf(a.y - __logf(fmaxf(d_gsum[g.y], FLT_EPSILON)), LOGEPS);
            r.z = fmaxf(a.z - __logf(fmaxf(d_gsum[g.z], FLT_EPSILON)), LOGEPS);
            r.w = fmaxf(a.w - __logf(fmaxf(d_gsum[g.w], FLT_EPSILON)), LOGEPS);
            ((float4*)out_edge)[i] = r;
        }
    }
}

// tail edges (only if E % 4 != 0)
__global__ void k_logits_tail(const int* __restrict__ batch, float* __restrict__ out,
                              int start, int E) {
    int e = start + blockIdx.x * blockDim.x + threadIdx.x;
    if (e >= E) return;
    out[e] = fmaxf(d_att[e] - __logf(fmaxf(d_gsum[batch[e]], FLT_EPSILON)), LOGEPS);
}

// ---------------- launch ----------------
extern "C" void kernel_launch(void* const* d_in, const int* in_sizes, int n_in,
                              void* d_out, int out_size) {
    const float* edge_tokens     = (const float*)d_in[0];
    const float* question_tokens = (const float*)d_in[1];
    const int*   edge_batch      = (const int*)d_in[2];
    const int*   selected_mask   = (const int*)d_in[3];
    const float* W_edge          = (const float*)d_in[4];
    const float* W_query         = (const float*)d_in[5];
    const float* att_vec         = (const float*)d_in[6];
    const float* ln_g            = (const float*)d_in[7];
    const float* ln_b            = (const float*)d_in[8];
    const float* W1              = (const float*)d_in[9];
    const float* b1              = (const float*)d_in[10];
    const float* W2              = (const float*)d_in[11];
    const float* b2              = (const float*)d_in[12];

    int E = in_sizes[2];
    float* out      = (float*)d_out;
    float* out_edge = out;             // [E]
    float* out_stop = out + E;         // [G]
    float* out_pool = out + E + G_;    // [G, H]

    k_uv<<<8, 256>>>(W_edge, W_query, att_vec);
    k_qatt<<<G_, 32>>>(question_tokens);
    // main pass: 4 blocks per SM (148*4 = 592), unroll-2
    {
        int blocks = 592, threads = 256;
        int warps = blocks * threads / 32;        // 4736
        int epw = (E + warps - 1) / warps;
        k_main<<<blocks, threads>>>(edge_tokens, edge_batch, selected_mask, E, epw);
    }
    // fused logits + head
    {
        int E4 = E / 4;
        int nblocks = NHEADB + (E4 + 511) / 512;
        k_post<<<nblocks, 256>>>(edge_batch, question_tokens, W_edge,
                                 ln_g, ln_b, W1, b1, W2, b2,
                                 out_edge, out_stop, out_pool, E4);
        int rem = E - E4 * 4;
        if (rem > 0)
            k_logits_tail<<<(rem + 255) / 256, 256>>>(edge_batch, out_edge, E4 * 4, E);
    }
}